// round 9
// baseline (speedup 1.0000x reference)
#include <cuda_runtime.h>
#include <cstdint>
#include <mma.h>
#include <math.h>

using namespace nvcuda;

#define B_   2
#define S_   2048
#define D_   2048
#define QH_  32
#define KVH_ 8
#define HD_  64
#define GRP_ 4

// ---------------- scratch (no allocations allowed) ----------------
__device__ float g_Q [(size_t)B_ * S_ * QH_  * HD_];
__device__ float g_K [(size_t)B_ * S_ * KVH_ * HD_];
__device__ float g_V [(size_t)B_ * S_ * KVH_ * HD_];
__device__ float g_AO[(size_t)B_ * S_ * QH_  * HD_];
__device__ float g_X [(size_t)B_ * S_ * D_];                  // rounded x
__device__ float g_Wr[(size_t)D_ * (QH_*HD_) * 2 + (size_t)D_ * (KVH_*HD_) * 2]; // rounded weights

#define WQ_OFF 0
#define WK_OFF ((size_t)D_ * (QH_*HD_))
#define WV_OFF (WK_OFF + (size_t)D_ * (KVH_*HD_))
#define WO_OFF (WV_OFF + (size_t)D_ * (KVH_*HD_))

// ---------------- helpers ----------------
__device__ __forceinline__ void cpa16(void* smem_dst, const void* gmem_src) {
    unsigned d = (unsigned)__cvta_generic_to_shared(smem_dst);
    asm volatile("cp.async.cg.shared.global [%0], [%1], 16;\n" :: "r"(d), "l"(gmem_src));
}
#define CP_COMMIT() asm volatile("cp.async.commit_group;\n" ::: "memory")
#define CP_WAIT0()  asm volatile("cp.async.wait_group 0;\n" ::: "memory")
#define CP_WAIT1()  asm volatile("cp.async.wait_group 1;\n" ::: "memory")

__device__ __forceinline__ float tf32r(float x) {
    unsigned r; asm("cvt.rna.tf32.f32 %0, %1;" : "=r"(r) : "f"(x));
    return __uint_as_float(r);
}

__device__ __forceinline__ void mma16n8k8(float* d, const unsigned* a, const unsigned* b) {
    asm volatile(
        "mma.sync.aligned.m16n8k8.row.col.f32.tf32.tf32.f32 "
        "{%0,%1,%2,%3}, {%4,%5,%6,%7}, {%8,%9}, {%0,%1,%2,%3};"
        : "+f"(d[0]), "+f"(d[1]), "+f"(d[2]), "+f"(d[3])
        : "r"(a[0]), "r"(a[1]), "r"(a[2]), "r"(a[3]), "r"(b[0]), "r"(b[1]));
}

// ---------------- elementwise tf32 rounding (float4) -----------------------
__global__ void round4_kernel(const float* __restrict__ in, float* __restrict__ out)
{
    int idx = blockIdx.x * blockDim.x + threadIdx.x;
    float4 v = ((const float4*)in)[idx];
    v.x = tf32r(v.x); v.y = tf32r(v.y); v.z = tf32r(v.z); v.w = tf32r(v.w);
    ((float4*)out)[idx] = v;
}

// ===================== TF32 GEMM + bias, double-buffered ===================
// Inputs MUST be pre-rounded to tf32. No cvt in the inner loop.
#define GA_SZ (128 * 36)
#define GB_SZ (32 * 132)
__global__ __launch_bounds__(256)
void gemm_tf32(const float* __restrict__ A, const float* __restrict__ W,
               const float* __restrict__ bias, float* __restrict__ C,
               int M, int N, int K)
{
    extern __shared__ float dsm[];
    float* As = dsm;
    float* Bs = dsm + 2 * GA_SZ;
    __shared__ float Bt[16 * 132];

    const int t      = threadIdx.x;
    const int warp   = t >> 5;
    const int warp_m = warp & 1;
    const int warp_n = warp >> 1;
    const int m0 = blockIdx.y * 128;
    const int n0 = blockIdx.x * 128;

    const int arow = t >> 2;
    const int avec = (t & 3) * 8;
    const int wrow = t >> 5;
    const int wcol = (t & 31) * 4;

    for (int e = t; e < 16 * 128; e += 256) {
        int r = e >> 7, c = e & 127;
        Bt[r * 132 + c] = bias[n0 + c];
    }

    wmma::fragment<wmma::accumulator, 16, 16, 8, float> acc[4][2];
    __syncthreads();
#pragma unroll
    for (int i = 0; i < 4; i++)
#pragma unroll
        for (int j = 0; j < 2; j++)
            wmma::load_matrix_sync(acc[i][j], &Bt[warp_n * 32 + j * 16], 132,
                                   wmma::mem_row_major);

    auto load_tile = [&](int k0, int buf) {
        float* Ab = As + buf * GA_SZ;
        float* Bb = Bs + buf * GB_SZ;
        cpa16(&Ab[arow * 36 + avec],            &A[(size_t)(m0 + arow)      * K + k0 + avec]);
        cpa16(&Ab[arow * 36 + avec + 4],        &A[(size_t)(m0 + arow)      * K + k0 + avec + 4]);
        cpa16(&Ab[(arow + 64) * 36 + avec],     &A[(size_t)(m0 + arow + 64) * K + k0 + avec]);
        cpa16(&Ab[(arow + 64) * 36 + avec + 4], &A[(size_t)(m0 + arow + 64) * K + k0 + avec + 4]);
        cpa16(&Bb[wrow * 132 + wcol],           &W[(size_t)(k0 + wrow)      * N + n0 + wcol]);
        cpa16(&Bb[(wrow +  8) * 132 + wcol],    &W[(size_t)(k0 + wrow +  8) * N + n0 + wcol]);
        cpa16(&Bb[(wrow + 16) * 132 + wcol],    &W[(size_t)(k0 + wrow + 16) * N + n0 + wcol]);
        cpa16(&Bb[(wrow + 24) * 132 + wcol],    &W[(size_t)(k0 + wrow + 24) * N + n0 + wcol]);
    };

    load_tile(0, 0);
    CP_COMMIT();

    for (int k0 = 0; k0 < K; k0 += 32) {
        const int buf = (k0 >> 5) & 1;
        if (k0 + 32 < K) { load_tile(k0 + 32, buf ^ 1); CP_COMMIT(); CP_WAIT1(); }
        else             { CP_WAIT0(); }
        __syncthreads();

        const float* Ab = As + buf * GA_SZ;
        const float* Bb = Bs + buf * GB_SZ;
#pragma unroll
        for (int kk = 0; kk < 32; kk += 8) {
            wmma::fragment<wmma::matrix_a, 16, 16, 8, wmma::precision::tf32,
                           wmma::row_major> af[4];
            wmma::fragment<wmma::matrix_b, 16, 16, 8, wmma::precision::tf32,
                           wmma::row_major> bf[2];
#pragma unroll
            for (int i = 0; i < 4; i++)
                wmma::load_matrix_sync(af[i], &Ab[(warp_m * 64 + i * 16) * 36 + kk], 36);
#pragma unroll
            for (int j = 0; j < 2; j++)
                wmma::load_matrix_sync(bf[j], &Bb[kk * 132 + warp_n * 32 + j * 16], 132);
#pragma unroll
            for (int i = 0; i < 4; i++)
#pragma unroll
                for (int j = 0; j < 2; j++)
                    wmma::mma_sync(acc[i][j], af[i], bf[j], acc[i][j]);
        }
        __syncthreads();
    }

#pragma unroll
    for (int i = 0; i < 4; i++)
#pragma unroll
        for (int j = 0; j < 2; j++)
            wmma::store_matrix_sync(
                &C[(size_t)(m0 + warp_m * 64 + i * 16) * N + n0 + warp_n * 32 + j * 16],
                acc[i][j], N, wmma::mem_row_major);
}

// ---------------- RoPE (in place), outputs tf32-rounded --------------------
__global__ void rope_kernel(float* __restrict__ X, const float* __restrict__ F,
                            int hshift, int total_pairs)
{
    int idx = blockIdx.x * blockDim.x + threadIdx.x;
    if (idx >= total_pairs) return;
    int p = idx & 31;
    int s = (idx >> (5 + hshift)) & (S_ - 1);
    float2 cs = ((const float2*)F)[s * 32 + p];
    float2 x  = ((float2*)X)[idx];
    float2 o;
    o.x = tf32r(x.x * cs.x - x.y * cs.y);
    o.y = tf32r(x.x * cs.y + x.y * cs.x);
    ((float2*)X)[idx] = o;
}

// ===================== FA2-style GQA attention (mma.sync tf32) =============
#define ALD 68
#define KV_SZ (64 * ALD)
__global__ __launch_bounds__(256)
void attn_mma(const float* __restrict__ Q, const float* __restrict__ K,
              const float* __restrict__ V, float* __restrict__ O)
{
    extern __shared__ float sm[];
    float* Qs = sm;                       // [128][68]  (also output staging)
    float* Sc = sm + 128 * ALD;           // [128][68]  P tile (warp-private rows)
    float* Ks = sm + 2 * 128 * ALD;       // [2][64][68]
    float* Vs = sm + 2 * 128 * ALD + 2 * KV_SZ;

    const int tid = threadIdx.x;
    const int w   = tid >> 5;
    const int l   = tid & 31;
    const int kh  = blockIdx.y;
    const int b   = blockIdx.z;
    const int q0  = blockIdx.x * 32;

    const int qr = l >> 2;
    const int qc = l & 3;
    const int row0 = 16 * w + qr;

    for (int e4 = tid; e4 < 2048; e4 += 256) {
        int r = e4 >> 4, c4 = (e4 & 15) * 4;
        int h = (kh << 2) + (r >> 5);
        int srow = q0 + (r & 31);
        float4 qv = *(const float4*)&Q[((size_t)(b * S_ + srow) * QH_ + h) * HD_ + c4];
        qv.x *= 0.125f; qv.y *= 0.125f; qv.z *= 0.125f; qv.w *= 0.125f;
        *(float4*)&Qs[r * ALD + c4] = qv;
    }

    const float* kb = K + (size_t)b * S_ * KVH_ * HD_ + kh * HD_;
    const float* vb = V + (size_t)b * S_ * KVH_ * HD_ + kh * HD_;

    auto load_kv = [&](int kt, int buf) {
        float* Kb = Ks + buf * KV_SZ;
        float* Vb = Vs + buf * KV_SZ;
        const float* kp = kb + (size_t)kt * 64 * (KVH_ * HD_);
        const float* vp = vb + (size_t)kt * 64 * (KVH_ * HD_);
#pragma unroll
        for (int i = 0; i < 4; i++) {
            int e4 = tid + i * 256;
            int r = e4 >> 4, c4 = (e4 & 15) * 4;
            cpa16(&Kb[r * ALD + c4], &kp[(size_t)r * (KVH_ * HD_) + c4]);
            cpa16(&Vb[r * ALD + c4], &vp[(size_t)r * (KVH_ * HD_) + c4]);
        }
    };

    float oacc[8][4];
#pragma unroll
    for (int j = 0; j < 8; j++)
#pragma unroll
        for (int e = 0; e < 4; e++) oacc[j][e] = 0.f;
    float m_a = -1e30f, m_b = -1e30f, l_a = 0.f, l_b = 0.f;

    load_kv(0, 0);
    CP_COMMIT();

    for (int kt = 0; kt < S_ / 64; kt++) {
        const int buf = kt & 1;
        CP_WAIT0();
        __syncthreads();
        if (kt + 1 < S_ / 64) { load_kv(kt + 1, buf ^ 1); CP_COMMIT(); }

        const float* Kb = Ks + buf * KV_SZ;
        const float* Vb = Vs + buf * KV_SZ;

        float sacc[8][4];
#pragma unroll
        for (int j = 0; j < 8; j++)
#pragma unroll
            for (int e = 0; e < 4; e++) sacc[j][e] = 0.f;

#pragma unroll
        for (int t = 0; t < 8; t++) {
            const int kc = t * 8;
            unsigned a[4];
            a[0] = __float_as_uint(Qs[(row0)     * ALD + kc + qc]);
            a[1] = __float_as_uint(Qs[(row0 + 8) * ALD + kc + qc]);
            a[2] = __float_as_uint(Qs[(row0)     * ALD + kc + qc + 4]);
            a[3] = __float_as_uint(Qs[(row0 + 8) * ALD + kc + qc + 4]);
#pragma unroll
            for (int j = 0; j < 8; j++) {
                unsigned bb[2];
                bb[0] = __float_as_uint(Kb[(8 * j + qr) * ALD + kc + qc]);
                bb[1] = __float_as_uint(Kb[(8 * j + qr) * ALD + kc + qc + 4]);
                mma16n8k8(sacc[j], a, bb);
            }
        }

        float ma = -1e30f, mb = -1e30f;
#pragma unroll
        for (int j = 0; j < 8; j++) {
            ma = fmaxf(ma, fmaxf(sacc[j][0], sacc[j][1]));
            mb = fmaxf(mb, fmaxf(sacc[j][2], sacc[j][3]));
        }
        ma = fmaxf(ma, __shfl_xor_sync(0xffffffffu, ma, 1));
        ma = fmaxf(ma, __shfl_xor_sync(0xffffffffu, ma, 2));
        mb = fmaxf(mb, __shfl_xor_sync(0xffffffffu, mb, 1));
        mb = fmaxf(mb, __shfl_xor_sync(0xffffffffu, mb, 2));

        float na = fmaxf(m_a, ma), nb = fmaxf(m_b, mb);
        float ca = __expf(m_a - na), cb = __expf(m_b - nb);
        float sa = 0.f, sb = 0.f;

#pragma unroll
        for (int j = 0; j < 8; j++) {
            float p0 = __expf(sacc[j][0] - na);
            float p1 = __expf(sacc[j][1] - na);
            float p2 = __expf(sacc[j][2] - nb);
            float p3 = __expf(sacc[j][3] - nb);
            sa += p0 + p1; sb += p2 + p3;
            const int cc = 8 * j + 2 * qc;
            *(float2*)&Sc[(row0)     * ALD + cc] = make_float2(tf32r(p0), tf32r(p1));
            *(float2*)&Sc[(row0 + 8) * ALD + cc] = make_float2(tf32r(p2), tf32r(p3));
            oacc[j][0] *= ca; oacc[j][1] *= ca;
            oacc[j][2] *= cb; oacc[j][3] *= cb;
        }
        sa += __shfl_xor_sync(0xffffffffu, sa, 1);
        sa += __shfl_xor_sync(0xffffffffu, sa, 2);
        sb += __shfl_xor_sync(0xffffffffu, sb, 1);
        sb += __shfl_xor_sync(0xffffffffu, sb, 2);
        l_a = l_a * ca + sa;  m_a = na;
        l_b = l_b * cb + sb;  m_b = nb;
        __syncwarp();

#pragma unroll
        for (int t = 0; t < 8; t++) {
            const int kc = t * 8;
            unsigned a[4];
            a[0] = __float_as_uint(Sc[(row0)     * ALD + kc + qc]);
            a[1] = __float_as_uint(Sc[(row0 + 8) * ALD + kc + qc]);
            a[2] = __float_as_uint(Sc[(row0)     * ALD + kc + qc + 4]);
            a[3] = __float_as_uint(Sc[(row0 + 8) * ALD + kc + qc + 4]);
#pragma unroll
            for (int j = 0; j < 8; j++) {
                unsigned bb[2];
                bb[0] = __float_as_uint(Vb[(kc + qc)     * ALD + 8 * j + qr]);
                bb[1] = __float_as_uint(Vb[(kc + qc + 4) * ALD + 8 * j + qr]);
                mma16n8k8(oacc[j], a, bb);
            }
        }
        __syncwarp();
    }

    // ---- finalize: 1/l scale + tf32 round (next GEMM's A operand) ----
    const float ia = 1.0f / l_a, ib = 1.0f / l_b;
#pragma unroll
    for (int j = 0; j < 8; j++) {
        const int cc = 8 * j + 2 * qc;
        *(float2*)&Qs[(row0)     * ALD + cc] =
            make_float2(tf32r(oacc[j][0] * ia), tf32r(oacc[j][1] * ia));
        *(float2*)&Qs[(row0 + 8) * ALD + cc] =
            make_float2(tf32r(oacc[j][2] * ib), tf32r(oacc[j][3] * ib));
    }
    __syncwarp();
#pragma unroll
    for (int i = 0; i < 8; i++) {
        int e4 = l + i * 32;
        int rr = e4 >> 4, c4 = (e4 & 15) * 4;
        int r = 16 * w + rr;
        int h = (kh << 2) + (r >> 5);
        int srow = q0 + (r & 31);
        *(float4*)&O[((size_t)(b * S_ + srow) * QH_ + h) * HD_ + c4] =
            *(float4*)&Qs[r * ALD + c4];
    }
}

// ---------------------------------------------------------------------------
extern "C" void kernel_launch(void* const* d_in, const int* in_sizes, int n_in,
                              void* d_out, int out_size)
{
    const float* x  = (const float*)d_in[0];
    const float* fr = (const float*)d_in[1];
    const float* Wq = (const float*)d_in[2];
    const float* bq = (const float*)d_in[3];
    const float* Wk = (const float*)d_in[4];
    const float* bk = (const float*)d_in[5];
    const float* Wv = (const float*)d_in[6];
    const float* bv = (const float*)d_in[7];
    const float* Wo = (const float*)d_in[8];
    const float* bo = (const float*)d_in[9];
    float* out = (float*)d_out;

    float *Qp, *Kp, *Vp, *AOp, *Xp, *Wr;
    cudaGetSymbolAddress((void**)&Qp,  g_Q);
    cudaGetSymbolAddress((void**)&Kp,  g_K);
    cudaGetSymbolAddress((void**)&Vp,  g_V);
    cudaGetSymbolAddress((void**)&AOp, g_AO);
    cudaGetSymbolAddress((void**)&Xp,  g_X);
    cudaGetSymbolAddress((void**)&Wr,  g_Wr);

    const int M = B_ * S_;   // 4096

    // ---- pre-round x and weights to tf32 (identical numerics to per-frag cvt) ----
    round4_kernel<<<(int)((size_t)M * D_ / 4 / 256), 256>>>(x, Xp);
    round4_kernel<<<(int)((size_t)D_ * (QH_*HD_) / 4 / 256), 256>>>(Wq, Wr + WQ_OFF);
    round4_kernel<<<(int)((size_t)D_ * (KVH_*HD_) / 4 / 256), 256>>>(Wk, Wr + WK_OFF);
    round4_kernel<<<(int)((size_t)D_ * (KVH_*HD_) / 4 / 256), 256>>>(Wv, Wr + WV_OFF);
    round4_kernel<<<(int)((size_t)D_ * (QH_*HD_) / 4 / 256), 256>>>(Wo, Wr + WO_OFF);

    const int gemm_smem = (2 * GA_SZ + 2 * GB_SZ) * sizeof(float);
    cudaFuncSetAttribute(gemm_tf32, cudaFuncAttributeMaxDynamicSharedMemorySize,
                         gemm_smem);

    gemm_tf32<<<dim3((QH_ * HD_) / 128, M / 128), 256, gemm_smem>>>(Xp, Wr + WQ_OFF, bq, Qp, M, QH_ * HD_, D_);
    gemm_tf32<<<dim3((KVH_ * HD_) / 128, M / 128), 256, gemm_smem>>>(Xp, Wr + WK_OFF, bk, Kp, M, KVH_ * HD_, D_);
    gemm_tf32<<<dim3((KVH_ * HD_) / 128, M / 128), 256, gemm_smem>>>(Xp, Wr + WV_OFF, bv, Vp, M, KVH_ * HD_, D_);

    {
        int totq = M * QH_ * 32;
        rope_kernel<<<totq / 256, 256>>>(Qp, fr, 5, totq);
        int totk = M * KVH_ * 32;
        rope_kernel<<<totk / 256, 256>>>(Kp, fr, 3, totk);
        int v4 = (int)((size_t)B_ * S_ * KVH_ * HD_ / 4);
        round4_kernel<<<v4 / 256, 256>>>(Vp, Vp);
    }

    const int attn_smem = (2 * 128 * ALD + 4 * KV_SZ) * sizeof(float);  // ~136 KB
    cudaFuncSetAttribute(attn_mma, cudaFuncAttributeMaxDynamicSharedMemorySize,
                         attn_smem);
    attn_mma<<<dim3(S_ / 32, KVH_, B_), 256, attn_smem>>>(Qp, Kp, Vp, AOp);

    gemm_tf32<<<dim3(D_ / 128, M / 128), 256, gemm_smem>>>(AOp, Wr + WO_OFF, bo, out, M, D_, D_);
}

// round 11
// speedup vs baseline: 1.5856x; 1.5856x over previous
#include <cuda_runtime.h>
#include <cstdint>
#include <math.h>

#define B_   2
#define S_   2048
#define D_   2048
#define QH_  32
#define KVH_ 8
#define HD_  64

// ---------------- scratch (no allocations allowed) ----------------
__device__ float g_Q [(size_t)B_ * S_ * QH_  * HD_];          // [M][2048]
__device__ float g_KV[(size_t)B_ * S_ * 1024];                // [M][1024] K|V
__device__ float g_AO[(size_t)B_ * S_ * QH_  * HD_];
__device__ float g_X [(size_t)B_ * S_ * D_];
__device__ float g_Wr[(size_t)D_ * 5120];                     // Wq | Wkv | Wo

#define WQ_OFF  ((size_t)0)
#define WKV_OFF ((size_t)D_ * 2048)
#define WO_OFF  ((size_t)D_ * 3072)

// ---------------- helpers ----------------
__device__ __forceinline__ void cpa16(void* smem_dst, const void* gmem_src) {
    unsigned d = (unsigned)__cvta_generic_to_shared(smem_dst);
    asm volatile("cp.async.cg.shared.global [%0], [%1], 16;\n" :: "r"(d), "l"(gmem_src));
}
#define CP_COMMIT() asm volatile("cp.async.commit_group;\n" ::: "memory")
#define CP_WAIT0()  asm volatile("cp.async.wait_group 0;\n" ::: "memory")
#define CP_WAIT2()  asm volatile("cp.async.wait_group 2;\n" ::: "memory")

__device__ __forceinline__ float tf32r(float x) {
    unsigned r; asm("cvt.rna.tf32.f32 %0, %1;" : "=r"(r) : "f"(x));
    return __uint_as_float(r);
}

__device__ __forceinline__ void mma16n8k8(float* d, const unsigned* a, const unsigned* b) {
    asm volatile(
        "mma.sync.aligned.m16n8k8.row.col.f32.tf32.tf32.f32 "
        "{%0,%1,%2,%3}, {%4,%5,%6,%7}, {%8,%9}, {%0,%1,%2,%3};"
        : "+f"(d[0]), "+f"(d[1]), "+f"(d[2]), "+f"(d[3])
        : "r"(a[0]), "r"(a[1]), "r"(a[2]), "r"(a[3]), "r"(b[0]), "r"(b[1]));
}

// ---------------- elementwise tf32 rounding (float4) -----------------------
__global__ void round4_kernel(const float* __restrict__ in, float* __restrict__ out)
{
    int idx = blockIdx.x * blockDim.x + threadIdx.x;
    float4 v = ((const float4*)in)[idx];
    v.x = tf32r(v.x); v.y = tf32r(v.y); v.z = tf32r(v.z); v.w = tf32r(v.w);
    ((float4*)out)[idx] = v;
}

// pack Wk|Wv -> [D][1024] interleaved columns, tf32-rounded
__global__ void roundkv_kernel(const float* __restrict__ Wk,
                               const float* __restrict__ Wv,
                               float* __restrict__ out)
{
    int idx = blockIdx.x * blockDim.x + threadIdx.x;   // float4 index over D*1024/4
    int r = idx >> 8;                                  // 256 float4 per row
    int c4 = (idx & 255) * 4;
    const float* src = (c4 < 512) ? &Wk[(size_t)r * 512 + c4]
                                  : &Wv[(size_t)r * 512 + (c4 - 512)];
    float4 v = *(const float4*)src;
    v.x = tf32r(v.x); v.y = tf32r(v.y); v.z = tf32r(v.z); v.w = tf32r(v.w);
    ((float4*)out)[idx] = v;
}

// ===================== raw-mma TF32 GEMM, 4-stage pipeline =================
// C[M,N] = A[M,K] @ W[K,N] (+bias, + fused epilogue). Operands pre-rounded.
// Block 128x256, BK=16, 8 warps, warp tile 64x64.
// MODE 0: +b1, store fp32 (final output)
// MODE 1: +b1, RoPE, tf32 round (Q projection)
// MODE 2: n<512: +b1,RoPE,round (K);  n>=512: +b2, round (V)
#define BM 128
#define BN 256
#define BK 16
#define GLDA 20
#define GLDB 264
#define ASTG (BM * GLDA)
#define BSTG (BK * GLDB)

template<int MODE>
__global__ __launch_bounds__(256, 1)
void gemm_raw(const float* __restrict__ A, const float* __restrict__ W,
              const float* __restrict__ b1, const float* __restrict__ b2,
              const float* __restrict__ F, float* __restrict__ C,
              int M, int N, int K)
{
    extern __shared__ float sh[];
    float* As = sh;                    // [4][ASTG]
    float* Bs = sh + 4 * ASTG;         // [4][BSTG]

    const int t    = threadIdx.x;
    const int warp = t >> 5, l = t & 31;
    const int qr   = l >> 2, qc = l & 3;
    const int wm   = warp & 1, wn = warp >> 1;
    const int m0   = blockIdx.y * BM;
    const int n0   = blockIdx.x * BN;

    auto load = [&](int tile, int s) {
        float* Ab = As + s * ASTG;
        float* Bb = Bs + s * BSTG;
        const int k0 = tile * BK;
#pragma unroll
        for (int i = 0; i < 2; i++) {
            int idx = t + i * 256;
            int r = idx >> 2, c4 = (idx & 3) * 4;
            cpa16(&Ab[r * GLDA + c4], &A[(size_t)(m0 + r) * K + k0 + c4]);
        }
#pragma unroll
        for (int i = 0; i < 4; i++) {
            int idx = t + i * 256;
            int r = idx >> 6, c4 = (idx & 63) * 4;
            cpa16(&Bb[r * GLDB + c4], &W[(size_t)(k0 + r) * N + n0 + c4]);
        }
        CP_COMMIT();
    };

    float acc[4][8][4];
#pragma unroll
    for (int i = 0; i < 4; i++)
#pragma unroll
        for (int j = 0; j < 8; j++)
#pragma unroll
            for (int e = 0; e < 4; e++) acc[i][j][e] = 0.f;

    const int ntiles = K / BK;
    load(0, 0); load(1, 1); load(2, 2);

    for (int it = 0; it < ntiles; it++) {
        CP_WAIT2();
        __syncthreads();
        const float* Ab = As + (it & 3) * ASTG;
        const float* Bb = Bs + (it & 3) * BSTG;
#pragma unroll
        for (int kk = 0; kk < BK; kk += 8) {
            unsigned a[4][4], bf[8][2];
#pragma unroll
            for (int i = 0; i < 4; i++) {
                const int r = wm * 64 + i * 16;
                a[i][0] = __float_as_uint(Ab[(r + qr)     * GLDA + kk + qc]);
                a[i][1] = __float_as_uint(Ab[(r + qr + 8) * GLDA + kk + qc]);
                a[i][2] = __float_as_uint(Ab[(r + qr)     * GLDA + kk + qc + 4]);
                a[i][3] = __float_as_uint(Ab[(r + qr + 8) * GLDA + kk + qc + 4]);
            }
#pragma unroll
            for (int j = 0; j < 8; j++) {
                const int n = wn * 64 + j * 8;
                bf[j][0] = __float_as_uint(Bb[(kk + qc)     * GLDB + n + qr]);
                bf[j][1] = __float_as_uint(Bb[(kk + qc + 4) * GLDB + n + qr]);
            }
#pragma unroll
            for (int i = 0; i < 4; i++)
#pragma unroll
                for (int j = 0; j < 8; j++)
                    mma16n8k8(acc[i][j], a[i], bf[j]);
        }
        if (it + 3 < ntiles) load(it + 3, (it + 3) & 3);
    }

    // ---- epilogue ----
#pragma unroll
    for (int i = 0; i < 4; i++) {
        const int rbase = m0 + wm * 64 + i * 16;
#pragma unroll
        for (int j = 0; j < 8; j++) {
            const int n_g = n0 + wn * 64 + j * 8 + 2 * qc;
#pragma unroll
            for (int half = 0; half < 2; half++) {
                const int row = rbase + qr + half * 8;
                float c0 = acc[i][j][half * 2 + 0];
                float c1 = acc[i][j][half * 2 + 1];
                if (MODE == 0 || MODE == 1) {
                    c0 += b1[n_g]; c1 += b1[n_g + 1];
                } else {
                    if (n_g < 512) { c0 += b1[n_g];      c1 += b1[n_g + 1]; }
                    else           { c0 += b2[n_g - 512]; c1 += b2[n_g - 511]; }
                }
                if (MODE == 1 || (MODE == 2 && n_g < 512)) {
                    const int s = row & (S_ - 1);
                    const int p = (n_g & 63) >> 1;
                    float2 cs = ((const float2*)F)[s * 32 + p];
                    float o0 = c0 * cs.x - c1 * cs.y;
                    float o1 = c0 * cs.y + c1 * cs.x;
                    c0 = tf32r(o0); c1 = tf32r(o1);
                } else if (MODE == 2) {
                    c0 = tf32r(c0); c1 = tf32r(c1);
                }
                *(float2*)&C[(size_t)row * N + n_g] = make_float2(c0, c1);
            }
        }
    }
}

// ===================== FA2-style GQA attention (mma.sync tf32) =============
#define ALD 68
#define KV_SZ (64 * ALD)
#define KVLD 1024
__global__ __launch_bounds__(256)
void attn_mma(const float* __restrict__ Q, const float* __restrict__ KV,
              float* __restrict__ O)
{
    extern __shared__ float sm[];
    float* Qs = sm;                       // [128][68]
    float* Sc = sm + 128 * ALD;           // [128][68]
    float* Ks = sm + 2 * 128 * ALD;       // [2][64][68]
    float* Vs = sm + 2 * 128 * ALD + 2 * KV_SZ;

    const int tid = threadIdx.x;
    const int w   = tid >> 5;
    const int l   = tid & 31;
    const int kh  = blockIdx.y;
    const int b   = blockIdx.z;
    const int q0  = blockIdx.x * 32;

    const int qr = l >> 2;
    const int qc = l & 3;
    const int row0 = 16 * w + qr;

    for (int e4 = tid; e4 < 2048; e4 += 256) {
        int r = e4 >> 4, c4 = (e4 & 15) * 4;
        int h = (kh << 2) + (r >> 5);
        int srow = q0 + (r & 31);
        float4 qv = *(const float4*)&Q[((size_t)(b * S_ + srow) * QH_ + h) * HD_ + c4];
        qv.x *= 0.125f; qv.y *= 0.125f; qv.z *= 0.125f; qv.w *= 0.125f;
        *(float4*)&Qs[r * ALD + c4] = qv;
    }

    const float* kb = KV + (size_t)b * S_ * KVLD + kh * HD_;
    const float* vb = kb + 512;

    auto load_kv = [&](int kt, int buf) {
        float* Kb = Ks + buf * KV_SZ;
        float* Vb = Vs + buf * KV_SZ;
        const float* kp = kb + (size_t)kt * 64 * KVLD;
        const float* vp = vb + (size_t)kt * 64 * KVLD;
#pragma unroll
        for (int i = 0; i < 4; i++) {
            int e4 = tid + i * 256;
            int r = e4 >> 4, c4 = (e4 & 15) * 4;
            cpa16(&Kb[r * ALD + c4], &kp[(size_t)r * KVLD + c4]);
            cpa16(&Vb[r * ALD + c4], &vp[(size_t)r * KVLD + c4]);
        }
    };

    float oacc[8][4];
#pragma unroll
    for (int j = 0; j < 8; j++)
#pragma unroll
        for (int e = 0; e < 4; e++) oacc[j][e] = 0.f;
    float m_a = -1e30f, m_b = -1e30f, l_a = 0.f, l_b = 0.f;

    load_kv(0, 0);
    CP_COMMIT();

    for (int kt = 0; kt < S_ / 64; kt++) {
        const int buf = kt & 1;
        CP_WAIT0();
        __syncthreads();
        if (kt + 1 < S_ / 64) { load_kv(kt + 1, buf ^ 1); CP_COMMIT(); }

        const float* Kb = Ks + buf * KV_SZ;
        const float* Vb = Vs + buf * KV_SZ;

        float sacc[8][4];
#pragma unroll
        for (int j = 0; j < 8; j++)
#pragma unroll
            for (int e = 0; e < 4; e++) sacc[j][e] = 0.f;

#pragma unroll
        for (int t = 0; t < 8; t++) {
            const int kc = t * 8;
            unsigned a[4];
            a[0] = __float_as_uint(Qs[(row0)     * ALD + kc + qc]);
            a[1] = __float_as_uint(Qs[(row0 + 8) * ALD + kc + qc]);
            a[2] = __float_as_uint(Qs[(row0)     * ALD + kc + qc + 4]);
            a[3] = __float_as_uint(Qs[(row0 + 8) * ALD + kc + qc + 4]);
#pragma unroll
            for (int j = 0; j < 8; j++) {
                unsigned bb[2];
                bb[0] = __float_as_uint(Kb[(8 * j + qr) * ALD + kc + qc]);
                bb[1] = __float_as_uint(Kb[(8 * j + qr) * ALD + kc + qc + 4]);
                mma16n8k8(sacc[j], a, bb);
            }
        }

        float ma = -1e30f, mb = -1e30f;
#pragma unroll
        for (int j = 0; j < 8; j++) {
            ma = fmaxf(ma, fmaxf(sacc[j][0], sacc[j][1]));
            mb = fmaxf(mb, fmaxf(sacc[j][2], sacc[j][3]));
        }
        ma = fmaxf(ma, __shfl_xor_sync(0xffffffffu, ma, 1));
        ma = fmaxf(ma, __shfl_xor_sync(0xffffffffu, ma, 2));
        mb = fmaxf(mb, __shfl_xor_sync(0xffffffffu, mb, 1));
        mb = fmaxf(mb, __shfl_xor_sync(0xffffffffu, mb, 2));

        float na = fmaxf(m_a, ma), nb = fmaxf(m_b, mb);
        float ca = __expf(m_a - na), cb = __expf(m_b - nb);
        float sa = 0.f, sb = 0.f;

#pragma unroll
        for (int j = 0; j < 8; j++) {
            float p0 = __expf(sacc[j][0] - na);
            float p1 = __expf(sacc[j][1] - na);
            float p2 = __expf(sacc[j][2] - nb);
            float p3 = __expf(sacc[j][3] - nb);
            sa += p0 + p1; sb += p2 + p3;
            const int cc = 8 * j + 2 * qc;
            *(float2*)&Sc[(row0)     * ALD + cc] = make_float2(tf32r(p0), tf32r(p1));
            *(float2*)&Sc[(row0 + 8) * ALD + cc] = make_float2(tf32r(p2), tf32r(p3));
            oacc[j][0] *= ca; oacc[j][1] *= ca;
            oacc[j][2] *= cb; oacc[j][3] *= cb;
        }
        sa += __shfl_xor_sync(0xffffffffu, sa, 1);
        sa += __shfl_xor_sync(0xffffffffu, sa, 2);
        sb += __shfl_xor_sync(0xffffffffu, sb, 1);
        sb += __shfl_xor_sync(0xffffffffu, sb, 2);
        l_a = l_a * ca + sa;  m_a = na;
        l_b = l_b * cb + sb;  m_b = nb;
        __syncwarp();

#pragma unroll
        for (int t = 0; t < 8; t++) {
            const int kc = t * 8;
            unsigned a[4];
            a[0] = __float_as_uint(Sc[(row0)     * ALD + kc + qc]);
            a[1] = __float_as_uint(Sc[(row0 + 8) * ALD + kc + qc]);
            a[2] = __float_as_uint(Sc[(row0)     * ALD + kc + qc + 4]);
            a[3] = __float_as_uint(Sc[(row0 + 8) * ALD + kc + qc + 4]);
#pragma unroll
            for (int j = 0; j < 8; j++) {
                unsigned bb[2];
                bb[0] = __float_as_uint(Vb[(kc + qc)     * ALD + 8 * j + qr]);
                bb[1] = __float_as_uint(Vb[(kc + qc + 4) * ALD + 8 * j + qr]);
                mma16n8k8(oacc[j], a, bb);
            }
        }
        __syncwarp();
    }

    const float ia = 1.0f / l_a, ib = 1.0f / l_b;
#pragma unroll
    for (int j = 0; j < 8; j++) {
        const int cc = 8 * j + 2 * qc;
        *(float2*)&Qs[(row0)     * ALD + cc] =
            make_float2(tf32r(oacc[j][0] * ia), tf32r(oacc[j][1] * ia));
        *(float2*)&Qs[(row0 + 8) * ALD + cc] =
            make_float2(tf32r(oacc[j][2] * ib), tf32r(oacc[j][3] * ib));
    }
    __syncwarp();
#pragma unroll
    for (int i = 0; i < 8; i++) {
        int e4 = l + i * 32;
        int rr = e4 >> 4, c4 = (e4 & 15) * 4;
        int r = 16 * w + rr;
        int h = (kh << 2) + (r >> 5);
        int srow = q0 + (r & 31);
        *(float4*)&O[((size_t)(b * S_ + srow) * QH_ + h) * HD_ + c4] =
            *(float4*)&Qs[r * ALD + c4];
    }
}

// ---------------------------------------------------------------------------
extern "C" void kernel_launch(void* const* d_in, const int* in_sizes, int n_in,
                              void* d_out, int out_size)
{
    const float* x  = (const float*)d_in[0];
    const float* fr = (const float*)d_in[1];
    const float* Wq = (const float*)d_in[2];
    const float* bq = (const float*)d_in[3];
    const float* Wk = (const float*)d_in[4];
    const float* bk = (const float*)d_in[5];
    const float* Wv = (const float*)d_in[6];
    const float* bv = (const float*)d_in[7];
    const float* Wo = (const float*)d_in[8];
    const float* bo = (const float*)d_in[9];
    float* out = (float*)d_out;

    float *Qp, *KVp, *AOp, *Xp, *Wr;
    cudaGetSymbolAddress((void**)&Qp,  g_Q);
    cudaGetSymbolAddress((void**)&KVp, g_KV);
    cudaGetSymbolAddress((void**)&AOp, g_AO);
    cudaGetSymbolAddress((void**)&Xp,  g_X);
    cudaGetSymbolAddress((void**)&Wr,  g_Wr);

    const int M = B_ * S_;   // 4096

    // ---- pre-round inputs / pack weights (tf32) ----
    round4_kernel<<<(int)((size_t)M * D_ / 4 / 256), 256>>>(x, Xp);
    round4_kernel<<<(int)((size_t)D_ * 2048 / 4 / 256), 256>>>(Wq, Wr + WQ_OFF);
    roundkv_kernel<<<(int)((size_t)D_ * 1024 / 4 / 256), 256>>>(Wk, Wv, Wr + WKV_OFF);
    round4_kernel<<<(int)((size_t)D_ * 2048 / 4 / 256), 256>>>(Wo, Wr + WO_OFF);

    const int gsmem = 4 * (ASTG + BSTG) * sizeof(float);   // ~106 KB
    cudaFuncSetAttribute(gemm_raw<0>, cudaFuncAttributeMaxDynamicSharedMemorySize, gsmem);
    cudaFuncSetAttribute(gemm_raw<1>, cudaFuncAttributeMaxDynamicSharedMemorySize, gsmem);
    cudaFuncSetAttribute(gemm_raw<2>, cudaFuncAttributeMaxDynamicSharedMemorySize, gsmem);

    // Q projection (+RoPE)  and fused K|V projection (+RoPE on K)
    gemm_raw<1><<<dim3(2048 / BN, M / BM), 256, gsmem>>>(
        Xp, Wr + WQ_OFF, bq, nullptr, fr, Qp, M, 2048, D_);
    gemm_raw<2><<<dim3(1024 / BN, M / BM), 256, gsmem>>>(
        Xp, Wr + WKV_OFF, bk, bv, fr, KVp, M, 1024, D_);

    const int attn_smem = (2 * 128 * ALD + 4 * KV_SZ) * sizeof(float);  // ~136 KB
    cudaFuncSetAttribute(attn_mma, cudaFuncAttributeMaxDynamicSharedMemorySize, attn_smem);
    attn_mma<<<dim3(S_ / 32, KVH_, B_), 256, attn_smem>>>(Qp, KVp, AOp);

    // output projection
    gemm_raw<0><<<dim3(2048 / BN, M / BM), 256, gsmem>>>(
        AOp, Wr + WO_OFF, bo, nullptr, nullptr, out, M, 2048, D_);
}

// round 12
// speedup vs baseline: 3.4057x; 2.1479x over previous
#include <cuda_runtime.h>
#include <cuda_fp16.h>
#include <cstdint>
#include <math.h>

#define B_   2
#define S_   2048
#define D_   2048
#define QH_  32
#define KVH_ 8
#define HD_  64

// ---------------- scratch (no allocations allowed) ----------------
// word = uint32 = half2
__device__ unsigned g_X16 [(size_t)B_ * S_ * 1024];            // x packed [M][K/2]
__device__ unsigned g_W16 [(size_t)5120 * 1024];               // Wq|Wkv|Wo packed [K/2][N]
__device__ unsigned g_Qh  [(size_t)B_ * S_ * 1024];            // Q  [M][2048 halfs]
__device__ unsigned g_Kh  [(size_t)B_ * S_ * 256];             // K  [M][512 halfs]
__device__ __half   g_Vt  [(size_t)B_ * KVH_ * 64 * S_];       // V transposed [b][kh][hd][S]
__device__ unsigned g_AO16[(size_t)B_ * S_ * 1024];            // attn out [M][2048 halfs]

#define WQ_OFF  ((size_t)0)
#define WKV_OFF ((size_t)1024 * 2048)
#define WO_OFF  ((size_t)1024 * 3072)

// ---------------- helpers ----------------
__device__ __forceinline__ void cpa16(void* smem_dst, const void* gmem_src) {
    unsigned d = (unsigned)__cvta_generic_to_shared(smem_dst);
    asm volatile("cp.async.cg.shared.global [%0], [%1], 16;\n" :: "r"(d), "l"(gmem_src));
}
#define CP_COMMIT() asm volatile("cp.async.commit_group;\n" ::: "memory")
#define CP_WAIT0()  asm volatile("cp.async.wait_group 0;\n" ::: "memory")
#define CP_WAIT2()  asm volatile("cp.async.wait_group 2;\n" ::: "memory")

__device__ __forceinline__ unsigned pack_h2(float a, float b) {
    __half2 h = __floats2half2_rn(a, b);
    return *(unsigned*)&h;
}

__device__ __forceinline__ void mma16n8k16h(float* d, const unsigned* a, const unsigned* b) {
    asm volatile(
        "mma.sync.aligned.m16n8k16.row.col.f32.f16.f16.f32 "
        "{%0,%1,%2,%3}, {%4,%5,%6,%7}, {%8,%9}, {%0,%1,%2,%3};"
        : "+f"(d[0]), "+f"(d[1]), "+f"(d[2]), "+f"(d[3])
        : "r"(a[0]), "r"(a[1]), "r"(a[2]), "r"(a[3]), "r"(b[0]), "r"(b[1]));
}

// ---------------- conversion kernels ----------------
// x [M][2048] f32 -> packed half2 words [M][1024]
__global__ void convX(const float* __restrict__ in, unsigned* __restrict__ out)
{
    int idx = blockIdx.x * blockDim.x + threadIdx.x;
    float2 v = ((const float2*)in)[idx];
    out[idx] = pack_h2(v.x, v.y);
}
// W [K][N] f32 -> words [K/2][N]: out[k'][n] = (W[2k'][n], W[2k'+1][n])
__global__ void convW(const float* __restrict__ W, unsigned* __restrict__ out, int N)
{
    int idx = blockIdx.x * blockDim.x + threadIdx.x;
    int kp = idx / N, n = idx - kp * N;
    out[idx] = pack_h2(W[(size_t)(2 * kp) * N + n], W[(size_t)(2 * kp + 1) * N + n]);
}
// Wk|Wv [2048][512] each -> words [1024][1024] (cols 0-511 Wk, 512-1023 Wv)
__global__ void convWkv(const float* __restrict__ Wk, const float* __restrict__ Wv,
                        unsigned* __restrict__ out)
{
    int idx = blockIdx.x * blockDim.x + threadIdx.x;
    int kp = idx >> 10, n = idx & 1023;
    const float* W = (n < 512) ? Wk : Wv;
    int nn = n & 511;
    out[idx] = pack_h2(W[(size_t)(2 * kp) * 512 + nn], W[(size_t)(2 * kp + 1) * 512 + nn]);
}

// ===================== fp16 GEMM, 4-stage pipeline =========================
// C[M,N] = A[M,K] @ W[K,N]. A words [M][K/2], W words [K/2][N].
// Block 128x256, BK=32 halfs (16 words), 8 warps, warp 64x64.
// MODE 0: +b1, store f32 (final out)
// MODE 1: +b1, RoPE, *0.125, -> half2 Q
// MODE 2: n<512: +b1, RoPE -> half2 K ; n>=512: +b2 -> V transposed halfs
#define BM 128
#define BN 256
#define GLDA 20
#define GLDB 264
#define ASTG (BM * GLDA)
#define BSTG (16 * GLDB)

template<int MODE>
__global__ __launch_bounds__(256, 1)
void gemm_h(const unsigned* __restrict__ A, const unsigned* __restrict__ W,
            const float* __restrict__ b1, const float* __restrict__ b2,
            const float* __restrict__ F, void* __restrict__ Cout,
            int M, int N, int K2)
{
    extern __shared__ unsigned sh[];
    unsigned* As = sh;                 // [4][ASTG]
    unsigned* Bs = sh + 4 * ASTG;      // [4][BSTG]

    const int t    = threadIdx.x;
    const int warp = t >> 5, l = t & 31;
    const int qr   = l >> 2, qc = l & 3;
    const int wm   = warp & 1, wn = warp >> 1;
    const int m0   = blockIdx.y * BM;
    const int n0   = blockIdx.x * BN;

    auto load = [&](int tile, int s) {
        unsigned* Ab = As + s * ASTG;
        unsigned* Bb = Bs + s * BSTG;
        const int k0 = tile * 16;
#pragma unroll
        for (int i = 0; i < 2; i++) {
            int idx = t + i * 256;
            int r = idx >> 2, c4 = (idx & 3) * 4;
            cpa16(&Ab[r * GLDA + c4], &A[(size_t)(m0 + r) * K2 + k0 + c4]);
        }
#pragma unroll
        for (int i = 0; i < 4; i++) {
            int idx = t + i * 256;
            int r = idx >> 6, c4 = (idx & 63) * 4;
            cpa16(&Bb[r * GLDB + c4], &W[(size_t)(k0 + r) * N + n0 + c4]);
        }
        CP_COMMIT();
    };

    float acc[4][8][4];
#pragma unroll
    for (int i = 0; i < 4; i++)
#pragma unroll
        for (int j = 0; j < 8; j++)
#pragma unroll
            for (int e = 0; e < 4; e++) acc[i][j][e] = 0.f;

    const int ntiles = K2 / 16;
    load(0, 0); load(1, 1); load(2, 2);

    for (int it = 0; it < ntiles; it++) {
        CP_WAIT2();
        __syncthreads();
        const unsigned* Ab = As + (it & 3) * ASTG;
        const unsigned* Bb = Bs + (it & 3) * BSTG;
#pragma unroll
        for (int step = 0; step < 2; step++) {
            const int kw = step * 8;
            unsigned a[4][4], bf[8][2];
#pragma unroll
            for (int i = 0; i < 4; i++) {
                const int r = wm * 64 + i * 16;
                a[i][0] = Ab[(r + qr)     * GLDA + kw + qc];
                a[i][1] = Ab[(r + qr + 8) * GLDA + kw + qc];
                a[i][2] = Ab[(r + qr)     * GLDA + kw + qc + 4];
                a[i][3] = Ab[(r + qr + 8) * GLDA + kw + qc + 4];
            }
#pragma unroll
            for (int j = 0; j < 8; j++) {
                const int n = wn * 64 + j * 8;
                bf[j][0] = Bb[(kw + qc)     * GLDB + n + qr];
                bf[j][1] = Bb[(kw + qc + 4) * GLDB + n + qr];
            }
#pragma unroll
            for (int i = 0; i < 4; i++)
#pragma unroll
                for (int j = 0; j < 8; j++)
                    mma16n8k16h(acc[i][j], a[i], bf[j]);
        }
        if (it + 3 < ntiles) load(it + 3, (it + 3) & 3);
    }

    // ---- epilogue ----
#pragma unroll
    for (int i = 0; i < 4; i++) {
        const int rbase = m0 + wm * 64 + i * 16;
#pragma unroll
        for (int j = 0; j < 8; j++) {
            const int n_g = n0 + wn * 64 + j * 8 + 2 * qc;
#pragma unroll
            for (int half = 0; half < 2; half++) {
                const int row = rbase + qr + half * 8;
                float c0 = acc[i][j][half * 2 + 0];
                float c1 = acc[i][j][half * 2 + 1];
                if (MODE == 0) {
                    c0 += b1[n_g]; c1 += b1[n_g + 1];
                    *(float2*)&((float*)Cout)[(size_t)row * N + n_g] = make_float2(c0, c1);
                } else if (MODE == 1) {
                    c0 += b1[n_g]; c1 += b1[n_g + 1];
                    const int s = row & (S_ - 1);
                    const int p = (n_g & 63) >> 1;
                    float2 cs = ((const float2*)F)[s * 32 + p];
                    float o0 = (c0 * cs.x - c1 * cs.y) * 0.125f;
                    float o1 = (c0 * cs.y + c1 * cs.x) * 0.125f;
                    ((unsigned*)Cout)[(size_t)row * 1024 + (n_g >> 1)] = pack_h2(o0, o1);
                } else {
                    if (n_g < 512) {
                        c0 += b1[n_g]; c1 += b1[n_g + 1];
                        const int s = row & (S_ - 1);
                        const int p = (n_g & 63) >> 1;
                        float2 cs = ((const float2*)F)[s * 32 + p];
                        float o0 = c0 * cs.x - c1 * cs.y;
                        float o1 = c0 * cs.y + c1 * cs.x;
                        ((unsigned*)Cout)[(size_t)row * 256 + (n_g >> 1)] = pack_h2(o0, o1);
                    } else {
                        c0 += b2[n_g - 512]; c1 += b2[n_g - 511];
                        const int vcol = n_g - 512;
                        const int khh = vcol >> 6, hd = vcol & 63;
                        const int bb = row >> 11, s = row & (S_ - 1);
                        __half* vt = g_Vt + ((size_t)(bb * KVH_ + khh) * 64) * S_ + s;
                        vt[(size_t)hd * S_]       = __float2half_rn(c0);
                        vt[(size_t)(hd + 1) * S_] = __float2half_rn(c1);
                    }
                }
            }
        }
    }
}

// ===================== FA2-style GQA attention (fp16 mma) ==================
// grid (S/32, KVH, B), 256 threads / 8 warps, 128-row Q tile (4 heads x 32).
#define QLD 36
#define KVT_SZ (64 * QLD)
__global__ __launch_bounds__(256)
void attn_h(const unsigned* __restrict__ Qh, const unsigned* __restrict__ Kh,
            const __half* __restrict__ Vt, unsigned* __restrict__ AO)
{
    extern __shared__ unsigned sm[];
    unsigned* Qs = sm;                     // [128][36]  Q words (also out staging)
    unsigned* Sc = sm + 128 * QLD;         // [128][36]  P words
    unsigned* Ks = sm + 2 * 128 * QLD;     // [2][64][36]
    unsigned* Vs = sm + 2 * 128 * QLD + 2 * KVT_SZ;

    const int tid = threadIdx.x;
    const int w   = tid >> 5;
    const int l   = tid & 31;
    const int kh  = blockIdx.y;
    const int b   = blockIdx.z;
    const int q0  = blockIdx.x * 32;

    const int qr = l >> 2;
    const int qc = l & 3;
    const int row0 = 16 * w + qr;

    // ---- load Q tile ----
    for (int e = tid; e < 1024; e += 256) {
        int r = e >> 3, w4 = (e & 7) * 4;
        int h = (kh << 2) + (r >> 5);
        int srow = q0 + (r & 31);
        *(uint4*)&Qs[r * QLD + w4] =
            *(const uint4*)&Qh[(size_t)(b * S_ + srow) * 1024 + h * 32 + w4];
    }

    const unsigned* kbase = Kh + (size_t)b * S_ * 256 + kh * 32;
    const unsigned* vbase = (const unsigned*)Vt + (size_t)((b * KVH_ + kh) * 64) * (S_ / 2);

    auto load_kv = [&](int kt, int buf) {
        unsigned* Kb = Ks + buf * KVT_SZ;
        unsigned* Vb = Vs + buf * KVT_SZ;
        const unsigned* kp = kbase + (size_t)kt * 64 * 256;
        const unsigned* vp = vbase + kt * 32;
#pragma unroll
        for (int i = 0; i < 2; i++) {
            int idx = tid + i * 256;            // 0..511
            int r = idx >> 3, w4 = (idx & 7) * 4;
            cpa16(&Kb[r * QLD + w4], &kp[(size_t)r * 256 + w4]);
            cpa16(&Vb[r * QLD + w4], &vp[(size_t)r * (S_ / 2) + w4]);
        }
    };

    float oacc[8][4];
#pragma unroll
    for (int j = 0; j < 8; j++)
#pragma unroll
        for (int e = 0; e < 4; e++) oacc[j][e] = 0.f;
    float m_a = -1e30f, m_b = -1e30f, l_a = 0.f, l_b = 0.f;

    load_kv(0, 0);
    CP_COMMIT();

    for (int kt = 0; kt < S_ / 64; kt++) {
        const int buf = kt & 1;
        CP_WAIT0();
        __syncthreads();
        if (kt + 1 < S_ / 64) { load_kv(kt + 1, buf ^ 1); CP_COMMIT(); }

        const unsigned* Kb = Ks + buf * KVT_SZ;
        const unsigned* Vb = Vs + buf * KVT_SZ;

        // ---- S = Q K^T ----
        float sacc[8][4];
#pragma unroll
        for (int j = 0; j < 8; j++)
#pragma unroll
            for (int e = 0; e < 4; e++) sacc[j][e] = 0.f;

#pragma unroll
        for (int t = 0; t < 4; t++) {
            const int kw = t * 8;
            unsigned a[4];
            a[0] = Qs[(row0)     * QLD + kw + qc];
            a[1] = Qs[(row0 + 8) * QLD + kw + qc];
            a[2] = Qs[(row0)     * QLD + kw + qc + 4];
            a[3] = Qs[(row0 + 8) * QLD + kw + qc + 4];
#pragma unroll
            for (int j = 0; j < 8; j++) {
                unsigned bb[2];
                bb[0] = Kb[(8 * j + qr) * QLD + kw + qc];
                bb[1] = Kb[(8 * j + qr) * QLD + kw + qc + 4];
                mma16n8k16h(sacc[j], a, bb);
            }
        }

        // ---- register online softmax ----
        float ma = -1e30f, mb = -1e30f;
#pragma unroll
        for (int j = 0; j < 8; j++) {
            ma = fmaxf(ma, fmaxf(sacc[j][0], sacc[j][1]));
            mb = fmaxf(mb, fmaxf(sacc[j][2], sacc[j][3]));
        }
        ma = fmaxf(ma, __shfl_xor_sync(0xffffffffu, ma, 1));
        ma = fmaxf(ma, __shfl_xor_sync(0xffffffffu, ma, 2));
        mb = fmaxf(mb, __shfl_xor_sync(0xffffffffu, mb, 1));
        mb = fmaxf(mb, __shfl_xor_sync(0xffffffffu, mb, 2));

        float na = fmaxf(m_a, ma), nb = fmaxf(m_b, mb);
        float ca = __expf(m_a - na), cb = __expf(m_b - nb);
        float sa = 0.f, sb = 0.f;

#pragma unroll
        for (int j = 0; j < 8; j++) {
            float p0 = __expf(sacc[j][0] - na);
            float p1 = __expf(sacc[j][1] - na);
            float p2 = __expf(sacc[j][2] - nb);
            float p3 = __expf(sacc[j][3] - nb);
            sa += p0 + p1; sb += p2 + p3;
            Sc[(row0)     * QLD + 4 * j + qc] = pack_h2(p0, p1);
            Sc[(row0 + 8) * QLD + 4 * j + qc] = pack_h2(p2, p3);
            oacc[j][0] *= ca; oacc[j][1] *= ca;
            oacc[j][2] *= cb; oacc[j][3] *= cb;
        }
        sa += __shfl_xor_sync(0xffffffffu, sa, 1);
        sa += __shfl_xor_sync(0xffffffffu, sa, 2);
        sb += __shfl_xor_sync(0xffffffffu, sb, 1);
        sb += __shfl_xor_sync(0xffffffffu, sb, 2);
        l_a = l_a * ca + sa;  m_a = na;
        l_b = l_b * cb + sb;  m_b = nb;
        __syncwarp();

        // ---- O += P V ----
#pragma unroll
        for (int t = 0; t < 4; t++) {
            const int kw = t * 8;
            unsigned a[4];
            a[0] = Sc[(row0)     * QLD + kw + qc];
            a[1] = Sc[(row0 + 8) * QLD + kw + qc];
            a[2] = Sc[(row0)     * QLD + kw + qc + 4];
            a[3] = Sc[(row0 + 8) * QLD + kw + qc + 4];
#pragma unroll
            for (int j = 0; j < 8; j++) {
                unsigned bb[2];
                bb[0] = Vb[(8 * j + qr) * QLD + kw + qc];
                bb[1] = Vb[(8 * j + qr) * QLD + kw + qc + 4];
                mma16n8k16h(oacc[j], a, bb);
            }
        }
        __syncwarp();
    }

    // ---- finalize: scale, pack half2, stage, coalesced store ----
    const float ia = 1.0f / l_a, ib = 1.0f / l_b;
#pragma unroll
    for (int j = 0; j < 8; j++) {
        Qs[(row0)     * QLD + 4 * j + qc] = pack_h2(oacc[j][0] * ia, oacc[j][1] * ia);
        Qs[(row0 + 8) * QLD + 4 * j + qc] = pack_h2(oacc[j][2] * ib, oacc[j][3] * ib);
    }
    __syncwarp();
#pragma unroll
    for (int i = 0; i < 4; i++) {
        int e = l + i * 32;                 // 0..127 over 16 rows x 8 uint4
        int rr = e >> 3, w4 = (e & 7) * 4;
        int r = 16 * w + rr;
        int h = (kh << 2) + (r >> 5);
        int srow = q0 + (r & 31);
        *(uint4*)&AO[(size_t)(b * S_ + srow) * 1024 + h * 32 + w4] =
            *(uint4*)&Qs[r * QLD + w4];
    }
}

// ---------------------------------------------------------------------------
extern "C" void kernel_launch(void* const* d_in, const int* in_sizes, int n_in,
                              void* d_out, int out_size)
{
    const float* x  = (const float*)d_in[0];
    const float* fr = (const float*)d_in[1];
    const float* Wq = (const float*)d_in[2];
    const float* bq = (const float*)d_in[3];
    const float* Wk = (const float*)d_in[4];
    const float* bk = (const float*)d_in[5];
    const float* Wv = (const float*)d_in[6];
    const float* bv = (const float*)d_in[7];
    const float* Wo = (const float*)d_in[8];
    const float* bo = (const float*)d_in[9];
    float* out = (float*)d_out;

    unsigned *X16, *W16, *Qh, *Kh, *AO16;
    __half* Vt;
    cudaGetSymbolAddress((void**)&X16,  g_X16);
    cudaGetSymbolAddress((void**)&W16,  g_W16);
    cudaGetSymbolAddress((void**)&Qh,   g_Qh);
    cudaGetSymbolAddress((void**)&Kh,   g_Kh);
    cudaGetSymbolAddress((void**)&Vt,   g_Vt);
    cudaGetSymbolAddress((void**)&AO16, g_AO16);

    const int M = B_ * S_;   // 4096

    // ---- pack fp32 -> fp16 ----
    convX  <<<(int)((size_t)M * 1024 / 256), 256>>>(x, X16);
    convW  <<<(int)((size_t)1024 * 2048 / 256), 256>>>(Wq, W16 + WQ_OFF, 2048);
    convWkv<<<(int)((size_t)1024 * 1024 / 256), 256>>>(Wk, Wv, W16 + WKV_OFF);
    convW  <<<(int)((size_t)1024 * 2048 / 256), 256>>>(Wo, W16 + WO_OFF, 2048);

    const int gsmem = 4 * (ASTG + BSTG) * sizeof(unsigned);   // ~108 KB
    cudaFuncSetAttribute(gemm_h<0>, cudaFuncAttributeMaxDynamicSharedMemorySize, gsmem);
    cudaFuncSetAttribute(gemm_h<1>, cudaFuncAttributeMaxDynamicSharedMemorySize, gsmem);
    cudaFuncSetAttribute(gemm_h<2>, cudaFuncAttributeMaxDynamicSharedMemorySize, gsmem);

    // Q projection (+RoPE, *0.125) ; fused K|V projection (+RoPE on K, V transposed)
    gemm_h<1><<<dim3(2048 / BN, M / BM), 256, gsmem>>>(
        X16, W16 + WQ_OFF, bq, nullptr, fr, Qh, M, 2048, 1024);
    gemm_h<2><<<dim3(1024 / BN, M / BM), 256, gsmem>>>(
        X16, W16 + WKV_OFF, bk, bv, fr, Kh, M, 1024, 1024);

    const int attn_smem = (2 * 128 * QLD + 4 * KVT_SZ) * sizeof(unsigned);  // ~74 KB
    cudaFuncSetAttribute(attn_h, cudaFuncAttributeMaxDynamicSharedMemorySize, attn_smem);
    attn_h<<<dim3(S_ / 32, KVH_, B_), 256, attn_smem>>>(Qh, Kh, Vt, AO16);

    // output projection (fp32 out)
    gemm_h<0><<<dim3(2048 / BN, M / BM), 256, gsmem>>>(
        AO16, W16 + WO_OFF, bo, nullptr, nullptr, out, M, 2048, 1024);
}

// round 14
// speedup vs baseline: 3.5755x; 1.0498x over previous
#include <cuda_runtime.h>
#include <cuda_fp16.h>
#include <cstdint>
#include <math.h>

#define B_   2
#define S_   2048
#define D_   2048
#define QH_  32
#define KVH_ 8
#define HD_  64

// ---------------- scratch (no allocations allowed) ----------------
// word = uint32 = half2
__device__ unsigned g_X16 [(size_t)B_ * S_ * 1024];            // x packed [M][K/2]
__device__ unsigned g_W16 [(size_t)5120 * 1024];               // W^T packed [n_total][K/2]
__device__ unsigned g_Qh  [(size_t)B_ * S_ * 1024];            // Q  [M][2048 halfs]
__device__ unsigned g_Kh  [(size_t)B_ * S_ * 256];             // K  [M][512 halfs]
__device__ __half   g_Vt  [(size_t)B_ * KVH_ * 64 * S_];       // V transposed [b][kh][hd][S]
__device__ unsigned g_AO16[(size_t)B_ * S_ * 1024];            // attn out [M][2048 halfs]

// W^T row offsets
#define WQ_ROW  0
#define WK_ROW  2048
#define WV_ROW  2560
#define WO_ROW  3072

// ---------------- helpers ----------------
__device__ __forceinline__ void cpa16(void* smem_dst, const void* gmem_src) {
    unsigned d = (unsigned)__cvta_generic_to_shared(smem_dst);
    asm volatile("cp.async.cg.shared.global [%0], [%1], 16;\n" :: "r"(d), "l"(gmem_src));
}
#define CP_COMMIT() asm volatile("cp.async.commit_group;\n" ::: "memory")
#define CP_WAIT0()  asm volatile("cp.async.wait_group 0;\n" ::: "memory")
#define CP_WAIT2()  asm volatile("cp.async.wait_group 2;\n" ::: "memory")

__device__ __forceinline__ unsigned pack_h2(float a, float b) {
    __half2 h = __floats2half2_rn(a, b);
    return *(unsigned*)&h;
}

__device__ __forceinline__ void mma16n8k16h(float* d, const unsigned* a, const unsigned* b) {
    asm volatile(
        "mma.sync.aligned.m16n8k16.row.col.f32.f16.f16.f32 "
        "{%0,%1,%2,%3}, {%4,%5,%6,%7}, {%8,%9}, {%0,%1,%2,%3};"
        : "+f"(d[0]), "+f"(d[1]), "+f"(d[2]), "+f"(d[3])
        : "r"(a[0]), "r"(a[1]), "r"(a[2]), "r"(a[3]), "r"(b[0]), "r"(b[1]));
}

__device__ __forceinline__ void ldsm4(unsigned& r0, unsigned& r1, unsigned& r2,
                                      unsigned& r3, unsigned saddr) {
    asm volatile("ldmatrix.sync.aligned.m8n8.x4.shared.b16 {%0,%1,%2,%3}, [%4];"
                 : "=r"(r0), "=r"(r1), "=r"(r2), "=r"(r3) : "r"(saddr));
}

// ---------------- conversion kernels ----------------
// x [M][2048] f32 -> packed half2 words [M][1024]
__global__ void convX(const float* __restrict__ in, unsigned* __restrict__ out)
{
    int idx = blockIdx.x * blockDim.x + threadIdx.x;
    float2 v = ((const float2*)in)[idx];
    out[idx] = pack_h2(v.x, v.y);
}
// W [K][N] f32 -> W^T packed [N][K/2] words, tiled transpose (coalesced both sides)
__global__ void convWt(const float* __restrict__ W, unsigned* __restrict__ out,
                       int N, int rowoff)
{
    __shared__ unsigned tile[32][33];
    const int kp0 = blockIdx.x * 32, n0 = blockIdx.y * 32;
    const int tx = threadIdx.x, ty = threadIdx.y;      // 32 x 8
#pragma unroll
    for (int i = 0; i < 32; i += 8) {
        int kp = kp0 + ty + i;
        int n  = n0 + tx;
        tile[ty + i][tx] = pack_h2(W[(size_t)(2 * kp) * N + n],
                                   W[(size_t)(2 * kp + 1) * N + n]);
    }
    __syncthreads();
#pragma unroll
    for (int i = 0; i < 32; i += 8) {
        int n  = n0 + ty + i;
        int kp = kp0 + tx;
        out[(size_t)(rowoff + n) * 1024 + kp] = tile[tx][ty + i];
    }
}

// ===================== fp16 GEMM, 4-stage pipeline, ldmatrix ===============
// C[M,N] = A[M,K] @ W[K,N]. A words [M][K2], W^T words [N][K2].
// Block 128x256, BK=32 halfs (16 words), 8 warps, warp 64x64.
// MODE 0: +b1, f32 out. MODE 1: +b1,RoPE,*0.125 -> Q half2.
// MODE 2: n<512: +b1,RoPE -> K half2 ; n>=512: +b2 -> g_Vt transposed.
#define BM 128
#define BN 256
#define APITCH 20
#define BPITCH 20
#define ASTG (BM * APITCH)
#define BSTG (BN * BPITCH)

template<int MODE>
__global__ __launch_bounds__(256, 1)
void gemm_h(const unsigned* __restrict__ A, const unsigned* __restrict__ Wt,
            const float* __restrict__ b1, const float* __restrict__ b2,
            const float* __restrict__ F, void* __restrict__ Cout,
            int M, int N, int K2)
{
    extern __shared__ unsigned sh[];
    unsigned* As = sh;                 // [4][ASTG]
    unsigned* Bs = sh + 4 * ASTG;      // [4][BSTG]

    const int t    = threadIdx.x;
    const int warp = t >> 5, l = t & 31;
    const int qr   = l >> 2, qc = l & 3;
    const int wm   = warp & 1, wn = warp >> 1;
    const int m0   = blockIdx.y * BM;
    const int n0   = blockIdx.x * BN;

    // ldmatrix lane geometry
    const int la8  = (l & 7) + ((l >> 3) & 1) * 8;   // A: rows 0-7|8-15, col by bit4
    const int acol = ((l >> 4) & 1) * 4;
    const int lb8  = (l & 7) + ((l >> 4) & 1) * 8;   // B: rows by bit4, col by bit3
    const int bcol = ((l >> 3) & 1) * 4;

    const unsigned as_b = (unsigned)__cvta_generic_to_shared(As);
    const unsigned bs_b = (unsigned)__cvta_generic_to_shared(Bs);
    unsigned a_addr[4], b_addr[4];
#pragma unroll
    for (int i = 0; i < 4; i++)
        a_addr[i] = as_b + ((wm * 64 + i * 16 + la8) * APITCH + acol) * 4;
#pragma unroll
    for (int jp = 0; jp < 4; jp++)
        b_addr[jp] = bs_b + ((wn * 64 + jp * 16 + lb8) * BPITCH + bcol) * 4;

    auto load = [&](int tile, int s) {
        unsigned* Ab = As + s * ASTG;
        unsigned* Bb = Bs + s * BSTG;
        const int k0 = tile * 16;
#pragma unroll
        for (int i = 0; i < 2; i++) {
            int idx = t + i * 256;
            int r = idx >> 2, c4 = (idx & 3) * 4;
            cpa16(&Ab[r * APITCH + c4], &A[(size_t)(m0 + r) * K2 + k0 + c4]);
        }
#pragma unroll
        for (int i = 0; i < 4; i++) {
            int idx = t + i * 256;
            int r = idx >> 2, c4 = (idx & 3) * 4;
            cpa16(&Bb[r * BPITCH + c4], &Wt[(size_t)(n0 + r) * K2 + k0 + c4]);
        }
        CP_COMMIT();
    };

    float acc[4][8][4];
#pragma unroll
    for (int i = 0; i < 4; i++)
#pragma unroll
        for (int j = 0; j < 8; j++)
#pragma unroll
            for (int e = 0; e < 4; e++) acc[i][j][e] = 0.f;

    const int ntiles = K2 / 16;
    load(0, 0); load(1, 1); load(2, 2);

    for (int it = 0; it < ntiles; it++) {
        CP_WAIT2();
        __syncthreads();
        const unsigned aoff = ((it & 3) * ASTG) * 4;
        const unsigned boff = ((it & 3) * BSTG) * 4;
#pragma unroll
        for (int step = 0; step < 2; step++) {
            const unsigned kwb = step * 8 * 4;
            unsigned a[4][4], bf[8][2];
#pragma unroll
            for (int i = 0; i < 4; i++)
                ldsm4(a[i][0], a[i][1], a[i][2], a[i][3], a_addr[i] + aoff + kwb);
#pragma unroll
            for (int jp = 0; jp < 4; jp++)
                ldsm4(bf[2 * jp][0], bf[2 * jp][1], bf[2 * jp + 1][0], bf[2 * jp + 1][1],
                      b_addr[jp] + boff + kwb);
#pragma unroll
            for (int i = 0; i < 4; i++)
#pragma unroll
                for (int j = 0; j < 8; j++)
                    mma16n8k16h(acc[i][j], a[i], bf[j]);
        }
        if (it + 3 < ntiles) load(it + 3, (it + 3) & 3);
    }

    // ---- epilogue ----
#pragma unroll
    for (int i = 0; i < 4; i++) {
        const int rbase = m0 + wm * 64 + i * 16;
#pragma unroll
        for (int j = 0; j < 8; j++) {
            const int n_g = n0 + wn * 64 + j * 8 + 2 * qc;
#pragma unroll
            for (int half = 0; half < 2; half++) {
                const int row = rbase + qr + half * 8;
                float c0 = acc[i][j][half * 2 + 0];
                float c1 = acc[i][j][half * 2 + 1];
                if (MODE == 0) {
                    c0 += b1[n_g]; c1 += b1[n_g + 1];
                    *(float2*)&((float*)Cout)[(size_t)row * N + n_g] = make_float2(c0, c1);
                } else if (MODE == 1) {
                    c0 += b1[n_g]; c1 += b1[n_g + 1];
                    const int s = row & (S_ - 1);
                    const int p = (n_g & 63) >> 1;
                    float2 cs = ((const float2*)F)[s * 32 + p];
                    float o0 = (c0 * cs.x - c1 * cs.y) * 0.125f;
                    float o1 = (c0 * cs.y + c1 * cs.x) * 0.125f;
                    ((unsigned*)Cout)[(size_t)row * 1024 + (n_g >> 1)] = pack_h2(o0, o1);
                } else {
                    if (n_g < 512) {
                        c0 += b1[n_g]; c1 += b1[n_g + 1];
                        const int s = row & (S_ - 1);
                        const int p = (n_g & 63) >> 1;
                        float2 cs = ((const float2*)F)[s * 32 + p];
                        float o0 = c0 * cs.x - c1 * cs.y;
                        float o1 = c0 * cs.y + c1 * cs.x;
                        ((unsigned*)Cout)[(size_t)row * 256 + (n_g >> 1)] = pack_h2(o0, o1);
                    } else {
                        c0 += b2[n_g - 512]; c1 += b2[n_g - 511];
                        const int vcol = n_g - 512;
                        const int khh = vcol >> 6, hd = vcol & 63;
                        const int bb = row >> 11, s = row & (S_ - 1);
                        __half* vt = g_Vt + ((size_t)(bb * KVH_ + khh) * 64) * S_ + s;
                        vt[(size_t)hd * S_]       = __float2half_rn(c0);
                        vt[(size_t)(hd + 1) * S_] = __float2half_rn(c1);
                    }
                }
            }
        }
    }
}

// ===================== FA2-style GQA attention (fp16 + ldmatrix) ===========
// grid (S/32, KVH, B), 256 threads / 8 warps, 128-row Q tile (4 heads x 32).
#define QLD 36
#define KVT_SZ (64 * QLD)
__global__ __launch_bounds__(256)
void attn_h(const unsigned* __restrict__ Qh, const unsigned* __restrict__ Kh,
            const __half* __restrict__ Vt, unsigned* __restrict__ AO)
{
    extern __shared__ unsigned sm[];
    unsigned* Qs = sm;                     // [128][36]
    unsigned* Sc = sm + 128 * QLD;         // [128][36]
    unsigned* Ks = sm + 2 * 128 * QLD;     // [2][64][36]
    unsigned* Vs = sm + 2 * 128 * QLD + 2 * KVT_SZ;

    const int tid = threadIdx.x;
    const int w   = tid >> 5;
    const int l   = tid & 31;
    const int kh  = blockIdx.y;
    const int b   = blockIdx.z;
    const int q0  = blockIdx.x * 32;

    const int qr = l >> 2;
    const int qc = l & 3;
    const int row0 = 16 * w + qr;

    const int la8  = (l & 7) + ((l >> 3) & 1) * 8;
    const int acol = ((l >> 4) & 1) * 4;
    const int lb8  = (l & 7) + ((l >> 4) & 1) * 8;
    const int bcol = ((l >> 3) & 1) * 4;

    const unsigned qs_b = (unsigned)__cvta_generic_to_shared(Qs);
    const unsigned sc_b = (unsigned)__cvta_generic_to_shared(Sc);
    const unsigned ks_b = (unsigned)__cvta_generic_to_shared(Ks);
    const unsigned vs_b = (unsigned)__cvta_generic_to_shared(Vs);
    const unsigned qa_addr = qs_b + (((16 * w + la8) * QLD) + acol) * 4;
    const unsigned pa_addr = sc_b + (((16 * w + la8) * QLD) + acol) * 4;
    unsigned kb_addr[4], vb_addr[4];
#pragma unroll
    for (int jp = 0; jp < 4; jp++) {
        kb_addr[jp] = ks_b + (((jp * 16 + lb8) * QLD) + bcol) * 4;
        vb_addr[jp] = vs_b + (((jp * 16 + lb8) * QLD) + bcol) * 4;
    }

    // ---- load Q tile ----
    for (int e = tid; e < 1024; e += 256) {
        int r = e >> 3, w4 = (e & 7) * 4;
        int h = (kh << 2) + (r >> 5);
        int srow = q0 + (r & 31);
        *(uint4*)&Qs[r * QLD + w4] =
            *(const uint4*)&Qh[(size_t)(b * S_ + srow) * 1024 + h * 32 + w4];
    }

    const unsigned* kbase = Kh + (size_t)b * S_ * 256 + kh * 32;
    const unsigned* vbase = (const unsigned*)Vt + (size_t)((b * KVH_ + kh) * 64) * (S_ / 2);

    auto load_kv = [&](int kt, int buf) {
        unsigned* Kb = Ks + buf * KVT_SZ;
        unsigned* Vb = Vs + buf * KVT_SZ;
        const unsigned* kp = kbase + (size_t)kt * 64 * 256;
        const unsigned* vp = vbase + kt * 32;
#pragma unroll
        for (int i = 0; i < 2; i++) {
            int idx = tid + i * 256;
            int r = idx >> 3, w4 = (idx & 7) * 4;
            cpa16(&Kb[r * QLD + w4], &kp[(size_t)r * 256 + w4]);
            cpa16(&Vb[r * QLD + w4], &vp[(size_t)r * (S_ / 2) + w4]);
        }
    };

    float oacc[8][4];
#pragma unroll
    for (int j = 0; j < 8; j++)
#pragma unroll
        for (int e = 0; e < 4; e++) oacc[j][e] = 0.f;
    float m_a = -1e30f, m_b = -1e30f, l_a = 0.f, l_b = 0.f;

    load_kv(0, 0);
    CP_COMMIT();

    for (int kt = 0; kt < S_ / 64; kt++) {
        const unsigned bufb = (kt & 1) * KVT_SZ * 4;
        CP_WAIT0();
        __syncthreads();
        if (kt + 1 < S_ / 64) { load_kv(kt + 1, (kt & 1) ^ 1); CP_COMMIT(); }

        // ---- S = Q K^T ----
        float sacc[8][4];
#pragma unroll
        for (int j = 0; j < 8; j++)
#pragma unroll
            for (int e = 0; e < 4; e++) sacc[j][e] = 0.f;

#pragma unroll
        for (int t4 = 0; t4 < 4; t4++) {
            const unsigned kwb = t4 * 8 * 4;
            unsigned a[4];
            ldsm4(a[0], a[1], a[2], a[3], qa_addr + kwb);
#pragma unroll
            for (int jp = 0; jp < 4; jp++) {
                unsigned b0, b1v, b2v, b3;
                ldsm4(b0, b1v, b2v, b3, kb_addr[jp] + bufb + kwb);
                unsigned be[2] = {b0, b1v}, bo[2] = {b2v, b3};
                mma16n8k16h(sacc[2 * jp],     a, be);
                mma16n8k16h(sacc[2 * jp + 1], a, bo);
            }
        }

        // ---- register online softmax ----
        float ma = -1e30f, mb = -1e30f;
#pragma unroll
        for (int j = 0; j < 8; j++) {
            ma = fmaxf(ma, fmaxf(sacc[j][0], sacc[j][1]));
            mb = fmaxf(mb, fmaxf(sacc[j][2], sacc[j][3]));
        }
        ma = fmaxf(ma, __shfl_xor_sync(0xffffffffu, ma, 1));
        ma = fmaxf(ma, __shfl_xor_sync(0xffffffffu, ma, 2));
        mb = fmaxf(mb, __shfl_xor_sync(0xffffffffu, mb, 1));
        mb = fmaxf(mb, __shfl_xor_sync(0xffffffffu, mb, 2));

        float na = fmaxf(m_a, ma), nb = fmaxf(m_b, mb);
        float ca = __expf(m_a - na), cb = __expf(m_b - nb);
        float sa = 0.f, sb = 0.f;

#pragma unroll
        for (int j = 0; j < 8; j++) {
            float p0 = __expf(sacc[j][0] - na);
            float p1 = __expf(sacc[j][1] - na);
            float p2 = __expf(sacc[j][2] - nb);
            float p3 = __expf(sacc[j][3] - nb);
            sa += p0 + p1; sb += p2 + p3;
            Sc[(row0)     * QLD + 4 * j + qc] = pack_h2(p0, p1);
            Sc[(row0 + 8) * QLD + 4 * j + qc] = pack_h2(p2, p3);
            oacc[j][0] *= ca; oacc[j][1] *= ca;
            oacc[j][2] *= cb; oacc[j][3] *= cb;
        }
        sa += __shfl_xor_sync(0xffffffffu, sa, 1);
        sa += __shfl_xor_sync(0xffffffffu, sa, 2);
        sb += __shfl_xor_sync(0xffffffffu, sb, 1);
        sb += __shfl_xor_sync(0xffffffffu, sb, 2);
        l_a = l_a * ca + sa;  m_a = na;
        l_b = l_b * cb + sb;  m_b = nb;
        __syncwarp();

        // ---- O += P V ----
#pragma unroll
        for (int t4 = 0; t4 < 4; t4++) {
            const unsigned kwb = t4 * 8 * 4;
            unsigned a[4];
            ldsm4(a[0], a[1], a[2], a[3], pa_addr + kwb);
#pragma unroll
            for (int jp = 0; jp < 4; jp++) {
                unsigned b0, b1v, b2v, b3;
                ldsm4(b0, b1v, b2v, b3, vb_addr[jp] + bufb + kwb);
                unsigned be[2] = {b0, b1v}, bo[2] = {b2v, b3};
                mma16n8k16h(oacc[2 * jp],     a, be);
                mma16n8k16h(oacc[2 * jp + 1], a, bo);
            }
        }
        __syncwarp();
    }

    // ---- finalize: scale, pack half2, stage, coalesced store ----
    const float ia = 1.0f / l_a, ib = 1.0f / l_b;
#pragma unroll
    for (int j = 0; j < 8; j++) {
        Qs[(row0)     * QLD + 4 * j + qc] = pack_h2(oacc[j][0] * ia, oacc[j][1] * ia);
        Qs[(row0 + 8) * QLD + 4 * j + qc] = pack_h2(oacc[j][2] * ib, oacc[j][3] * ib);
    }
    __syncwarp();
#pragma unroll
    for (int i = 0; i < 4; i++) {
        int e = l + i * 32;
        int rr = e >> 3, w4 = (e & 7) * 4;
        int r = 16 * w + rr;
        int h = (kh << 2) + (r >> 5);
        int srow = q0 + (r & 31);
        *(uint4*)&AO[(size_t)(b * S_ + srow) * 1024 + h * 32 + w4] =
            *(uint4*)&Qs[r * QLD + w4];
    }
}

// ---------------------------------------------------------------------------
extern "C" void kernel_launch(void* const* d_in, const int* in_sizes, int n_in,
                              void* d_out, int out_size)
{
    const float* x  = (const float*)d_in[0];
    const float* fr = (const float*)d_in[1];
    const float* Wq = (const float*)d_in[2];
    const float* bq = (const float*)d_in[3];
    const float* Wk = (const float*)d_in[4];
    const float* bk = (const float*)d_in[5];
    const float* Wv = (const float*)d_in[6];
    const float* bv = (const float*)d_in[7];
    const float* Wo = (const float*)d_in[8];
    const float* bo = (const float*)d_in[9];
    float* out = (float*)d_out;

    unsigned *X16, *W16, *Qh, *Kh, *AO16;
    __half* Vt;
    cudaGetSymbolAddress((void**)&X16,  g_X16);
    cudaGetSymbolAddress((void**)&W16,  g_W16);
    cudaGetSymbolAddress((void**)&Qh,   g_Qh);
    cudaGetSymbolAddress((void**)&Kh,   g_Kh);
    cudaGetSymbolAddress((void**)&Vt,   g_Vt);
    cudaGetSymbolAddress((void**)&AO16, g_AO16);

    const int M = B_ * S_;   // 4096

    // ---- pack fp32 -> fp16 (weights transposed) ----
    convX <<<(int)((size_t)M * 1024 / 256), 256>>>(x, X16);
    {
        dim3 blk(32, 8);
        convWt<<<dim3(32, 2048 / 32), blk>>>(Wq, W16, 2048, WQ_ROW);
        convWt<<<dim3(32,  512 / 32), blk>>>(Wk, W16,  512, WK_ROW);
        convWt<<<dim3(32,  512 / 32), blk>>>(Wv, W16,  512, WV_ROW);
        convWt<<<dim3(32, 2048 / 32), blk>>>(Wo, W16, 2048, WO_ROW);
    }

    const int gsmem = 4 * (ASTG + BSTG) * sizeof(unsigned);   // ~123 KB
    cudaFuncSetAttribute(gemm_h<0>, cudaFuncAttributeMaxDynamicSharedMemorySize, gsmem);
    cudaFuncSetAttribute(gemm_h<1>, cudaFuncAttributeMaxDynamicSharedMemorySize, gsmem);
    cudaFuncSetAttribute(gemm_h<2>, cudaFuncAttributeMaxDynamicSharedMemorySize, gsmem);

    // Q projection (+RoPE, *0.125) ; fused K|V projection (+RoPE on K, V transposed)
    gemm_h<1><<<dim3(2048 / BN, M / BM), 256, gsmem>>>(
        X16, W16 + (size_t)WQ_ROW * 1024, bq, nullptr, fr, Qh, M, 2048, 1024);
    gemm_h<2><<<dim3(1024 / BN, M / BM), 256, gsmem>>>(
        X16, W16 + (size_t)WK_ROW * 1024, bk, bv, fr, Kh, M, 1024, 1024);

    const int attn_smem = (2 * 128 * QLD + 4 * KVT_SZ) * sizeof(unsigned);  // ~74 KB
    cudaFuncSetAttribute(attn_h, cudaFuncAttributeMaxDynamicSharedMemorySize, attn_smem);
    attn_h<<<dim3(S_ / 32, KVH_, B_), 256, attn_smem>>>(Qh, Kh, Vt, AO16);

    // output projection (fp32 out)
    gemm_h<0><<<dim3(2048 / BN, M / BM), 256, gsmem>>>(
        AO16, W16 + (size_t)WO_ROW * 1024, bo, nullptr, nullptr, out, M, 2048, 1024);
}

// round 17
// speedup vs baseline: 3.6792x; 1.0290x over previous
#include <cuda_runtime.h>
#include <cuda_fp16.h>
#include <cstdint>
#include <math.h>

#define B_   2
#define S_   2048
#define D_   2048
#define QH_  32
#define KVH_ 8
#define HD_  64

// ---------------- scratch (no allocations allowed) ----------------
// word = uint32 = half2
__device__ unsigned g_X16 [(size_t)B_ * S_ * 1024];            // x packed [M][K/2]
__device__ unsigned g_W16 [(size_t)5120 * 1024];               // W^T packed [n_total][K/2]
__device__ unsigned g_Qh  [(size_t)B_ * S_ * 1024];            // Q  [M][2048 halfs]
__device__ unsigned g_Kh  [(size_t)B_ * S_ * 256];             // K  [M][512 halfs]
__device__ __half   g_Vt  [(size_t)B_ * KVH_ * 64 * S_];       // V transposed [b][kh][hd][S]
__device__ unsigned g_AO16[(size_t)B_ * S_ * 1024];            // attn out [M][2048 halfs]

// W^T row offsets
#define WQ_ROW  0
#define WK_ROW  2048
#define WV_ROW  2560
#define WO_ROW  3072

// ---------------- helpers ----------------
__device__ __forceinline__ void cpa16(void* smem_dst, const void* gmem_src) {
    unsigned d = (unsigned)__cvta_generic_to_shared(smem_dst);
    asm volatile("cp.async.cg.shared.global [%0], [%1], 16;\n" :: "r"(d), "l"(gmem_src));
}
#define CP_COMMIT() asm volatile("cp.async.commit_group;\n" ::: "memory")
#define CP_WAIT0()  asm volatile("cp.async.wait_group 0;\n" ::: "memory")
#define CP_WAIT2()  asm volatile("cp.async.wait_group 2;\n" ::: "memory")

__device__ __forceinline__ unsigned pack_h2(float a, float b) {
    __half2 h = __floats2half2_rn(a, b);
    return *(unsigned*)&h;
}

__device__ __forceinline__ float ex2(float x) {
    float r; asm("ex2.approx.f32 %0, %1;" : "=f"(r) : "f"(x));
    return r;
}

__device__ __forceinline__ void mma16n8k16h(float* d, const unsigned* a, const unsigned* b) {
    asm volatile(
        "mma.sync.aligned.m16n8k16.row.col.f32.f16.f16.f32 "
        "{%0,%1,%2,%3}, {%4,%5,%6,%7}, {%8,%9}, {%0,%1,%2,%3};"
        : "+f"(d[0]), "+f"(d[1]), "+f"(d[2]), "+f"(d[3])
        : "r"(a[0]), "r"(a[1]), "r"(a[2]), "r"(a[3]), "r"(b[0]), "r"(b[1]));
}

__device__ __forceinline__ void ldsm4(unsigned& r0, unsigned& r1, unsigned& r2,
                                      unsigned& r3, unsigned saddr) {
    asm volatile("ldmatrix.sync.aligned.m8n8.x4.shared.b16 {%0,%1,%2,%3}, [%4];"
                 : "=r"(r0), "=r"(r1), "=r"(r2), "=r"(r3) : "r"(saddr));
}

// ---------------- conversion kernels ----------------
__global__ void convX(const float* __restrict__ in, unsigned* __restrict__ out)
{
    int idx = blockIdx.x * blockDim.x + threadIdx.x;
    float2 v = ((const float2*)in)[idx];
    out[idx] = pack_h2(v.x, v.y);
}
// W [K][N] f32 -> W^T packed [N][K/2] words, tiled transpose
__global__ void convWt(const float* __restrict__ W, unsigned* __restrict__ out,
                       int N, int rowoff)
{
    __shared__ unsigned tile[32][33];
    const int kp0 = blockIdx.x * 32, n0 = blockIdx.y * 32;
    const int tx = threadIdx.x, ty = threadIdx.y;      // 32 x 8
#pragma unroll
    for (int i = 0; i < 32; i += 8) {
        int kp = kp0 + ty + i;
        int n  = n0 + tx;
        tile[ty + i][tx] = pack_h2(W[(size_t)(2 * kp) * N + n],
                                   W[(size_t)(2 * kp + 1) * N + n]);
    }
    __syncthreads();
#pragma unroll
    for (int i = 0; i < 32; i += 8) {
        int n  = n0 + ty + i;
        int kp = kp0 + tx;
        out[(size_t)(rowoff + n) * 1024 + kp] = tile[tx][ty + i];
    }
}

// ===================== fp16 GEMM, 4-stage pipeline, ldmatrix ===============
// Block 128x128, BK=32 halfs (16 words), 8 warps, warp 64x32, 2 CTAs/SM.
// MODE 0: +b1, f32 out. MODE 1: +b1,RoPE,*0.125*log2e -> Q half2.
// MODE 2: n<512: +b1,RoPE -> K half2 ; n>=512: +b2 -> g_Vt transposed.
#define BM 128
#define BN 128
#define APITCH 20
#define BPITCH 20
#define ASTG (BM * APITCH)
#define BSTG (BN * BPITCH)

template<int MODE>
__global__ __launch_bounds__(256, 2)
void gemm_h(const unsigned* __restrict__ A, const unsigned* __restrict__ Wt,
            const float* __restrict__ b1, const float* __restrict__ b2,
            const float* __restrict__ F, void* __restrict__ Cout,
            int M, int N, int K2)
{
    extern __shared__ unsigned sh[];
    unsigned* As = sh;                 // [4][ASTG]
    unsigned* Bs = sh + 4 * ASTG;      // [4][BSTG]

    const int t    = threadIdx.x;
    const int warp = t >> 5, l = t & 31;
    const int qr   = l >> 2, qc = l & 3;
    const int wm   = warp & 1, wn = warp >> 1;   // 2 x 4 warps, warp 64x32
    const int m0   = blockIdx.y * BM;
    const int n0   = blockIdx.x * BN;

    const int la8  = (l & 7) + ((l >> 3) & 1) * 8;
    const int acol = ((l >> 4) & 1) * 4;
    const int lb8  = (l & 7) + ((l >> 4) & 1) * 8;
    const int bcol = ((l >> 3) & 1) * 4;

    const unsigned as_b = (unsigned)__cvta_generic_to_shared(As);
    const unsigned bs_b = (unsigned)__cvta_generic_to_shared(Bs);
    unsigned a_addr[4], b_addr[2];
#pragma unroll
    for (int i = 0; i < 4; i++)
        a_addr[i] = as_b + ((wm * 64 + i * 16 + la8) * APITCH + acol) * 4;
#pragma unroll
    for (int jp = 0; jp < 2; jp++)
        b_addr[jp] = bs_b + ((wn * 32 + jp * 16 + lb8) * BPITCH + bcol) * 4;

    auto load = [&](int tile, int s) {
        unsigned* Ab = As + s * ASTG;
        unsigned* Bb = Bs + s * BSTG;
        const int k0 = tile * 16;
#pragma unroll
        for (int i = 0; i < 2; i++) {
            int idx = t + i * 256;
            int r = idx >> 2, c4 = (idx & 3) * 4;
            cpa16(&Ab[r * APITCH + c4], &A[(size_t)(m0 + r) * K2 + k0 + c4]);
            cpa16(&Bb[r * BPITCH + c4], &Wt[(size_t)(n0 + r) * K2 + k0 + c4]);
        }
        CP_COMMIT();
    };

    float acc[4][4][4];
#pragma unroll
    for (int i = 0; i < 4; i++)
#pragma unroll
        for (int j = 0; j < 4; j++)
#pragma unroll
            for (int e = 0; e < 4; e++) acc[i][j][e] = 0.f;

    const int ntiles = K2 / 16;
    load(0, 0); load(1, 1); load(2, 2);

    for (int it = 0; it < ntiles; it++) {
        CP_WAIT2();
        __syncthreads();
        const unsigned aoff = ((it & 3) * ASTG) * 4;
        const unsigned boff = ((it & 3) * BSTG) * 4;
#pragma unroll
        for (int step = 0; step < 2; step++) {
            const unsigned kwb = step * 8 * 4;
            unsigned a[4][4], bf[4][2];
#pragma unroll
            for (int i = 0; i < 4; i++)
                ldsm4(a[i][0], a[i][1], a[i][2], a[i][3], a_addr[i] + aoff + kwb);
#pragma unroll
            for (int jp = 0; jp < 2; jp++)
                ldsm4(bf[2 * jp][0], bf[2 * jp][1], bf[2 * jp + 1][0], bf[2 * jp + 1][1],
                      b_addr[jp] + boff + kwb);
#pragma unroll
            for (int i = 0; i < 4; i++)
#pragma unroll
                for (int j = 0; j < 4; j++)
                    mma16n8k16h(acc[i][j], a[i], bf[j]);
        }
        if (it + 3 < ntiles) load(it + 3, (it + 3) & 3);
    }

    // ---- epilogue ----
#pragma unroll
    for (int i = 0; i < 4; i++) {
        const int rbase = m0 + wm * 64 + i * 16;
#pragma unroll
        for (int j = 0; j < 4; j++) {
            const int n_g = n0 + wn * 32 + j * 8 + 2 * qc;
#pragma unroll
            for (int half = 0; half < 2; half++) {
                const int row = rbase + qr + half * 8;
                float c0 = acc[i][j][half * 2 + 0];
                float c1 = acc[i][j][half * 2 + 1];
                if (MODE == 0) {
                    c0 += b1[n_g]; c1 += b1[n_g + 1];
                    *(float2*)&((float*)Cout)[(size_t)row * N + n_g] = make_float2(c0, c1);
                } else if (MODE == 1) {
                    c0 += b1[n_g]; c1 += b1[n_g + 1];
                    const int s = row & (S_ - 1);
                    const int p = (n_g & 63) >> 1;
                    float2 cs = ((const float2*)F)[s * 32 + p];
                    // scale = 1/8 * log2(e)  (softmax done base-2)
                    const float sc = 0.1803368801111204f;
                    float o0 = (c0 * cs.x - c1 * cs.y) * sc;
                    float o1 = (c0 * cs.y + c1 * cs.x) * sc;
                    ((unsigned*)Cout)[(size_t)row * 1024 + (n_g >> 1)] = pack_h2(o0, o1);
                } else {
                    if (n_g < 512) {
                        c0 += b1[n_g]; c1 += b1[n_g + 1];
                        const int s = row & (S_ - 1);
                        const int p = (n_g & 63) >> 1;
                        float2 cs = ((const float2*)F)[s * 32 + p];
                        float o0 = c0 * cs.x - c1 * cs.y;
                        float o1 = c0 * cs.y + c1 * cs.x;
                        ((unsigned*)Cout)[(size_t)row * 256 + (n_g >> 1)] = pack_h2(o0, o1);
                    } else {
                        c0 += b2[n_g - 512]; c1 += b2[n_g - 511];
                        const int vcol = n_g - 512;
                        const int khh = vcol >> 6, hd = vcol & 63;
                        const int bb = row >> 11, s = row & (S_ - 1);
                        __half* vt = g_Vt + ((size_t)(bb * KVH_ + khh) * 64) * S_ + s;
                        vt[(size_t)hd * S_]       = __float2half_rn(c0);
                        vt[(size_t)(hd + 1) * S_] = __float2half_rn(c1);
                    }
                }
            }
        }
    }
}

// ===================== FA2-style GQA attention (fp16 + ldmatrix) ===========
// grid (S/32, KVH, B), 256 threads / 8 warps, 128-row Q tile (4 heads x 32).
// Softmax in base-2 (Q pre-scaled by log2e/8).
#define QLD 36
#define KVT_SZ (64 * QLD)
__global__ __launch_bounds__(256)
void attn_h(const unsigned* __restrict__ Qh, const unsigned* __restrict__ Kh,
            const __half* __restrict__ Vt, unsigned* __restrict__ AO)
{
    extern __shared__ unsigned sm[];
    unsigned* Qs = sm;                     // [128][36]
    unsigned* Sc = sm + 128 * QLD;         // [128][36]
    unsigned* Ks = sm + 2 * 128 * QLD;     // [2][64][36]
    unsigned* Vs = sm + 2 * 128 * QLD + 2 * KVT_SZ;

    const int tid = threadIdx.x;
    const int w   = tid >> 5;
    const int l   = tid & 31;
    const int kh  = blockIdx.y;
    const int b   = blockIdx.z;
    const int q0  = blockIdx.x * 32;

    const int qr = l >> 2;
    const int qc = l & 3;
    const int row0 = 16 * w + qr;

    const int la8  = (l & 7) + ((l >> 3) & 1) * 8;
    const int acol = ((l >> 4) & 1) * 4;
    const int lb8  = (l & 7) + ((l >> 4) & 1) * 8;
    const int bcol = ((l >> 3) & 1) * 4;

    const unsigned qs_b = (unsigned)__cvta_generic_to_shared(Qs);
    const unsigned sc_b = (unsigned)__cvta_generic_to_shared(Sc);
    const unsigned ks_b = (unsigned)__cvta_generic_to_shared(Ks);
    const unsigned vs_b = (unsigned)__cvta_generic_to_shared(Vs);
    const unsigned qa_addr = qs_b + (((16 * w + la8) * QLD) + acol) * 4;
    const unsigned pa_addr = sc_b + (((16 * w + la8) * QLD) + acol) * 4;
    unsigned kb_addr[4], vb_addr[4];
#pragma unroll
    for (int jp = 0; jp < 4; jp++) {
        kb_addr[jp] = ks_b + (((jp * 16 + lb8) * QLD) + bcol) * 4;
        vb_addr[jp] = vs_b + (((jp * 16 + lb8) * QLD) + bcol) * 4;
    }

    // ---- load Q tile ----
    for (int e = tid; e < 1024; e += 256) {
        int r = e >> 3, w4 = (e & 7) * 4;
        int h = (kh << 2) + (r >> 5);
        int srow = q0 + (r & 31);
        *(uint4*)&Qs[r * QLD + w4] =
            *(const uint4*)&Qh[(size_t)(b * S_ + srow) * 1024 + h * 32 + w4];
    }

    const unsigned* kbase = Kh + (size_t)b * S_ * 256 + kh * 32;
    const unsigned* vbase = (const unsigned*)Vt + (size_t)((b * KVH_ + kh) * 64) * (S_ / 2);

    auto load_kv = [&](int kt, int buf) {
        unsigned* Kb = Ks + buf * KVT_SZ;
        unsigned* Vb = Vs + buf * KVT_SZ;
        const unsigned* kp = kbase + (size_t)kt * 64 * 256;
        const unsigned* vp = vbase + kt * 32;
#pragma unroll
        for (int i = 0; i < 2; i++) {
            int idx = tid + i * 256;
            int r = idx >> 3, w4 = (idx & 7) * 4;
            cpa16(&Kb[r * QLD + w4], &kp[(size_t)r * 256 + w4]);
            cpa16(&Vb[r * QLD + w4], &vp[(size_t)r * (S_ / 2) + w4]);
        }
    };

    float oacc[8][4];
#pragma unroll
    for (int j = 0; j < 8; j++)
#pragma unroll
        for (int e = 0; e < 4; e++) oacc[j][e] = 0.f;
    float m_a = -1e30f, m_b = -1e30f, l_a = 0.f, l_b = 0.f;

    load_kv(0, 0);
    CP_COMMIT();

    for (int kt = 0; kt < S_ / 64; kt++) {
        const unsigned bufb = (kt & 1) * KVT_SZ * 4;
        CP_WAIT0();
        __syncthreads();
        if (kt + 1 < S_ / 64) { load_kv(kt + 1, (kt & 1) ^ 1); CP_COMMIT(); }

        // ---- S = Q K^T (scores already in log2 units) ----
        float sacc[8][4];
#pragma unroll
        for (int j = 0; j < 8; j++)
#pragma unroll
            for (int e = 0; e < 4; e++) sacc[j][e] = 0.f;

#pragma unroll
        for (int t4 = 0; t4 < 4; t4++) {
            const unsigned kwb = t4 * 8 * 4;
            unsigned a[4];
            ldsm4(a[0], a[1], a[2], a[3], qa_addr + kwb);
#pragma unroll
            for (int jp = 0; jp < 4; jp++) {
                unsigned b0, b1v, b2v, b3;
                ldsm4(b0, b1v, b2v, b3, kb_addr[jp] + bufb + kwb);
                unsigned be[2] = {b0, b1v}, bo[2] = {b2v, b3};
                mma16n8k16h(sacc[2 * jp],     a, be);
                mma16n8k16h(sacc[2 * jp + 1], a, bo);
            }
        }

        // ---- register online softmax (base-2) ----
        float ma = -1e30f, mb = -1e30f;
#pragma unroll
        for (int j = 0; j < 8; j++) {
            ma = fmaxf(ma, fmaxf(sacc[j][0], sacc[j][1]));
            mb = fmaxf(mb, fmaxf(sacc[j][2], sacc[j][3]));
        }
        ma = fmaxf(ma, __shfl_xor_sync(0xffffffffu, ma, 1));
        ma = fmaxf(ma, __shfl_xor_sync(0xffffffffu, ma, 2));
        mb = fmaxf(mb, __shfl_xor_sync(0xffffffffu, mb, 1));
        mb = fmaxf(mb, __shfl_xor_sync(0xffffffffu, mb, 2));

        float na = fmaxf(m_a, ma), nb = fmaxf(m_b, mb);
        float ca = ex2(m_a - na), cb = ex2(m_b - nb);
        float sa = 0.f, sb = 0.f;

#pragma unroll
        for (int j = 0; j < 8; j++) {
            float p0 = ex2(sacc[j][0] - na);
            float p1 = ex2(sacc[j][1] - na);
            float p2 = ex2(sacc[j][2] - nb);
            float p3 = ex2(sacc[j][3] - nb);
            sa += p0 + p1; sb += p2 + p3;
            Sc[(row0)     * QLD + 4 * j + qc] = pack_h2(p0, p1);
            Sc[(row0 + 8) * QLD + 4 * j + qc] = pack_h2(p2, p3);
            oacc[j][0] *= ca; oacc[j][1] *= ca;
            oacc[j][2] *= cb; oacc[j][3] *= cb;
        }
        sa += __shfl_xor_sync(0xffffffffu, sa, 1);
        sa += __shfl_xor_sync(0xffffffffu, sa, 2);
        sb += __shfl_xor_sync(0xffffffffu, sb, 1);
        sb += __shfl_xor_sync(0xffffffffu, sb, 2);
        l_a = l_a * ca + sa;  m_a = na;
        l_b = l_b * cb + sb;  m_b = nb;
        __syncwarp();

        // ---- O += P V ----
#pragma unroll
        for (int t4 = 0; t4 < 4; t4++) {
            const unsigned kwb = t4 * 8 * 4;
            unsigned a[4];
            ldsm4(a[0], a[1], a[2], a[3], pa_addr + kwb);
#pragma unroll
            for (int jp = 0; jp < 4; jp++) {
                unsigned b0, b1v, b2v, b3;
                ldsm4(b0, b1v, b2v, b3, vb_addr[jp] + bufb + kwb);
                unsigned be[2] = {b0, b1v}, bo[2] = {b2v, b3};
                mma16n8k16h(oacc[2 * jp],     a, be);
                mma16n8k16h(oacc[2 * jp + 1], a, bo);
            }
        }
        __syncwarp();
    }

    // ---- finalize ----
    const float ia = 1.0f / l_a, ib = 1.0f / l_b;
#pragma unroll
    for (int j = 0; j < 8; j++) {
        Qs[(row0)     * QLD + 4 * j + qc] = pack_h2(oacc[j][0] * ia, oacc[j][1] * ia);
        Qs[(row0 + 8) * QLD + 4 * j + qc] = pack_h2(oacc[j][2] * ib, oacc[j][3] * ib);
    }
    __syncwarp();
#pragma unroll
    for (int i = 0; i < 4; i++) {
        int e = l + i * 32;
        int rr = e >> 3, w4 = (e & 7) * 4;
        int r = 16 * w + rr;
        int h = (kh << 2) + (r >> 5);
        int srow = q0 + (r & 31);
        *(uint4*)&AO[(size_t)(b * S_ + srow) * 1024 + h * 32 + w4] =
            *(uint4*)&Qs[r * QLD + w4];
    }
}

// ---------------------------------------------------------------------------
extern "C" void kernel_launch(void* const* d_in, const int* in_sizes, int n_in,
                              void* d_out, int out_size)
{
    const float* x  = (const float*)d_in[0];
    const float* fr = (const float*)d_in[1];
    const float* Wq = (const float*)d_in[2];
    const float* bq = (const float*)d_in[3];
    const float* Wk = (const float*)d_in[4];
    const float* bk = (const float*)d_in[5];
    const float* Wv = (const float*)d_in[6];
    const float* bv = (const float*)d_in[7];
    const float* Wo = (const float*)d_in[8];
    const float* bo = (const float*)d_in[9];
    float* out = (float*)d_out;

    unsigned *X16, *W16, *Qh, *Kh, *AO16;
    __half* Vt;
    cudaGetSymbolAddress((void**)&X16,  g_X16);
    cudaGetSymbolAddress((void**)&W16,  g_W16);
    cudaGetSymbolAddress((void**)&Qh,   g_Qh);
    cudaGetSymbolAddress((void**)&Kh,   g_Kh);
    cudaGetSymbolAddress((void**)&Vt,   g_Vt);
    cudaGetSymbolAddress((void**)&AO16, g_AO16);

    const int M = B_ * S_;   // 4096

    // ---- pack fp32 -> fp16 (weights transposed) ----
    convX <<<(int)((size_t)M * 1024 / 256), 256>>>(x, X16);
    {
        dim3 blk(32, 8);
        convWt<<<dim3(32, 2048 / 32), blk>>>(Wq, W16, 2048, WQ_ROW);
        convWt<<<dim3(32,  512 / 32), blk>>>(Wk, W16,  512, WK_ROW);
        convWt<<<dim3(32,  512 / 32), blk>>>(Wv, W16,  512, WV_ROW);
        convWt<<<dim3(32, 2048 / 32), blk>>>(Wo, W16, 2048, WO_ROW);
    }

    const int gsmem = 4 * (ASTG + BSTG) * sizeof(unsigned);   // 80 KB
    cudaFuncSetAttribute(gemm_h<0>, cudaFuncAttributeMaxDynamicSharedMemorySize, gsmem);
    cudaFuncSetAttribute(gemm_h<1>, cudaFuncAttributeMaxDynamicSharedMemorySize, gsmem);
    cudaFuncSetAttribute(gemm_h<2>, cudaFuncAttributeMaxDynamicSharedMemorySize, gsmem);

    // Q projection (+RoPE, *log2e/8) ; fused K|V projection (+RoPE on K, V transposed)
    gemm_h<1><<<dim3(2048 / BN, M / BM), 256, gsmem>>>(
        X16, W16 + (size_t)WQ_ROW * 1024, bq, nullptr, fr, Qh, M, 2048, 1024);
    gemm_h<2><<<dim3(1024 / BN, M / BM), 256, gsmem>>>(
        X16, W16 + (size_t)WK_ROW * 1024, bk, bv, fr, Kh, M, 1024, 1024);

    const int attn_smem = (2 * 128 * QLD + 4 * KVT_SZ) * sizeof(unsigned);  // ~74 KB
    cudaFuncSetAttribute(attn_h, cudaFuncAttributeMaxDynamicSharedMemorySize, attn_smem);
    attn_h<<<dim3(S_ / 32, KVH_, B_), 256, attn_smem>>>(Qh, Kh, Vt, AO16);

    // output projection (fp32 out)
    gemm_h<0><<<dim3(2048 / BN, M / BM), 256, gsmem>>>(
        AO16, W16 + (size_t)WO_ROW * 1024, bo, nullptr, nullptr, out, M, 2048, 1024);
}